// round 3
// baseline (speedup 1.0000x reference)
#include <cuda_runtime.h>

#define TV 6400           // T*V = 256*25
#define NBATCH 64

// ---------------- scratch (device globals; no allocation allowed) ----------
__device__ float g_ab[78643200];    // (64,192,6400): a/b conv out, REUSED as xs
__device__ float g_z[104857600];    // (64,256,6400): [y | down] pre-BN
__device__ float g_part[480000];    // (4,64,3,625) split-K logits partials
__device__ float g_S[120000];       // (64,3,25,25) final mixing matrix
__device__ float g_Atot[1875];      // A + PA
__device__ float g_Wab[12288];      // (192,64) stacked Wa|Wb
__device__ float g_bab[192];
__device__ float g_Wdc[24576];      // (128,192) Wd re-laid [o][i*64+c]
__device__ float g_by[128];         // sum_i bd[i]
__device__ float g_alpha[256];      // BN fused scale
__device__ float g_bet[256];        // BN fused shift

// ---------------- prep: repack weights, A+PA ------------------------------
__global__ __launch_bounds__(256) void prep_kernel(
    const float* __restrict__ Wa, const float* __restrict__ ba,
    const float* __restrict__ Wb, const float* __restrict__ bb,
    const float* __restrict__ Wd, const float* __restrict__ bd,
    const float* __restrict__ A,  const float* __restrict__ PA)
{
    int stride = gridDim.x * blockDim.x;
    int g = blockIdx.x * blockDim.x + threadIdx.x;
    for (int f = g; f < 12288; f += stride)
        g_Wab[f] = (f < 6144) ? Wa[f] : Wb[f - 6144];
    for (int f = g; f < 192; f += stride)
        g_bab[f] = (f < 96) ? ba[f] : bb[f - 96];
    for (int f = g; f < 24576; f += stride) {
        int o = f / 192, r = f - o * 192;       // r = i*64 + c
        int i = r >> 6, c = r & 63;
        g_Wdc[f] = Wd[(i * 128 + o) * 64 + c];
    }
    for (int f = g; f < 128; f += stride)
        g_by[f] = bd[f] + bd[128 + f] + bd[256 + f];
    for (int f = g; f < 1875; f += stride)
        g_Atot[f] = A[f] + PA[f];
}

// ---------------- shared GEMM core: OUT[n,m,p] = W[m,:]·IN[n,:,p] + bias ---
// Block tile: 64 M x 128 P, K-chunks of 32. Thread micro-tile 4x8.
template <int K>
__device__ __forceinline__ void gemm_core(
    const float* __restrict__ IN, long in_ns,
    const float* __restrict__ W,  const float* __restrict__ bias,
    float* __restrict__ OUT, long out_ns)
{
    __shared__ float Ws[32][68];     // [k][m], padded (68: f4-aligned, no bank conflict)
    __shared__ float Is[32][128];    // [k][p]
    int tid = threadIdx.x;
    int tm = tid >> 4, tp = tid & 15;
    int n = blockIdx.z;
    int mBase = blockIdx.y * 64;
    int pBase = blockIdx.x * 128;
    const float* in_n = IN + (long)n * in_ns + pBase;

    float acc[4][8];
#pragma unroll
    for (int i = 0; i < 4; i++)
#pragma unroll
        for (int j = 0; j < 8; j++) acc[i][j] = 0.f;

    for (int kc = 0; kc < K; kc += 32) {
#pragma unroll
        for (int f = tid; f < 2048; f += 256) {          // W tile (coalesced rows)
            int m = f >> 5, k = f & 31;
            Ws[k][m] = W[(mBase + m) * K + kc + k];
        }
#pragma unroll
        for (int f = tid; f < 4096; f += 256) {          // IN tile (coalesced)
            int k = f >> 7, p = f & 127;
            Is[k][p] = in_n[(long)(kc + k) * TV + p];
        }
        __syncthreads();
#pragma unroll
        for (int k = 0; k < 32; k++) {
            float4 w4 = *(const float4*)&Ws[k][tm * 4];
            float4 a4 = *(const float4*)&Is[k][tp * 8];
            float4 b4 = *(const float4*)&Is[k][tp * 8 + 4];
            float wv[4] = {w4.x, w4.y, w4.z, w4.w};
            float iv[8] = {a4.x, a4.y, a4.z, a4.w, b4.x, b4.y, b4.z, b4.w};
#pragma unroll
            for (int i = 0; i < 4; i++)
#pragma unroll
                for (int j = 0; j < 8; j++)
                    acc[i][j] = fmaf(wv[i], iv[j], acc[i][j]);
        }
        __syncthreads();
    }
#pragma unroll
    for (int i = 0; i < 4; i++) {
        int m = mBase + tm * 4 + i;
        float b = bias[m];
        float* op = OUT + (long)n * out_ns + (long)m * TV + pBase + tp * 8;
        float4 o0 = make_float4(acc[i][0] + b, acc[i][1] + b, acc[i][2] + b, acc[i][3] + b);
        float4 o1 = make_float4(acc[i][4] + b, acc[i][5] + b, acc[i][6] + b, acc[i][7] + b);
        *(float4*)op = o0;
        *(float4*)(op + 4) = o1;
    }
}

__global__ __launch_bounds__(256) void gemm_ab(const float* __restrict__ x) {
    gemm_core<64>(x, 64L * TV, g_Wab, g_bab, g_ab, 192L * TV);
}
__global__ __launch_bounds__(256) void gemm_y() {
    gemm_core<192>(g_ab, 192L * TV, g_Wdc, g_by, g_z, 256L * TV);
}
__global__ __launch_bounds__(256) void gemm_down(const float* __restrict__ x,
                                                 const float* __restrict__ Wdown,
                                                 const float* __restrict__ bdown) {
    gemm_core<64>(x, 64L * TV, Wdown, bdown, g_z + 128L * TV, 256L * TV);
}

// ---------------- logits: lg[n,i,v,w] = sum_{r,t} a[...v]*b[...w] ----------
// Split-K over blockIdx.z (4 splits). 8 k-groups x 25 positions, 5x5 tiles.
// Deterministic (no atomics): per-kgroup partials reduced through smem.
__global__ __launch_bounds__(256) void logits_kernel() {
    int i = blockIdx.x, n = blockIdx.y, ks = blockIdx.z;
    __shared__ float As[1600], Bs[1600];   // 64 k-slots x 25
    __shared__ float part[8][625];
    int tid = threadIdx.x;
    int kg = tid >> 5, lane = tid & 31;
    bool active = lane < 25;
    int vb = (lane / 5) * 5, wb = (lane % 5) * 5;
    float acc[5][5];
#pragma unroll
    for (int a = 0; a < 5; a++)
#pragma unroll
        for (int b = 0; b < 5; b++) acc[a][b] = 0.f;

    const float* abase = g_ab + ((long)n * 192 + i * 32) * TV;
    const float* bbase = abase + 96L * TV;

    for (int c = ks * 32; c < ks * 32 + 32; c++) {
        int r = c >> 2, t0 = (c & 3) * 64;          // chunk = 64 t-values of channel r
        const float* ap = abase + (long)r * TV + t0 * 25;
        const float* bp = bbase + (long)r * TV + t0 * 25;
        __syncthreads();
        for (int f = tid; f < 1600; f += 256) { As[f] = ap[f]; Bs[f] = bp[f]; }
        __syncthreads();
        if (active) {
#pragma unroll
            for (int kk = 0; kk < 8; kk++) {
                int kb = (kg * 8 + kk) * 25;
                float av[5], bv[5];
#pragma unroll
                for (int a = 0; a < 5; a++) av[a] = As[kb + vb + a];
#pragma unroll
                for (int b = 0; b < 5; b++) bv[b] = Bs[kb + wb + b];
#pragma unroll
                for (int a = 0; a < 5; a++)
#pragma unroll
                    for (int b = 0; b < 5; b++)
                        acc[a][b] = fmaf(av[a], bv[b], acc[a][b]);
            }
        }
    }
    __syncthreads();
    if (active)
#pragma unroll
        for (int a = 0; a < 5; a++)
#pragma unroll
            for (int b = 0; b < 5; b++)
                part[kg][(vb + a) * 25 + wb + b] = acc[a][b];
    __syncthreads();
    float* outp = g_part + ((long)ks * 192 + n * 3 + i) * 625;
    for (int f = tid; f < 625; f += 256) {
        float s = part[0][f] + part[1][f] + part[2][f] + part[3][f]
                + part[4][f] + part[5][f] + part[6][f] + part[7][f];
        outp[f] = s;
    }
}

// ---------------- softmax over v (axis=1) per (n,i,w), + A_tot ------------
__global__ __launch_bounds__(256) void softmax_kernel() {
    int gid = blockIdx.x * blockDim.x + threadIdx.x;
    if (gid >= 64 * 3 * 25) return;
    int w = gid % 25;
    int i = (gid / 25) % 3;
    int n = gid / 75;
    const float* pp = g_part + (n * 3 + i) * 625 + w;
    float lg[25];
    float mx = -1e30f;
#pragma unroll
    for (int v = 0; v < 25; v++) {
        float s = (pp[v * 25] + pp[120000 + v * 25] + pp[240000 + v * 25]
                   + pp[360000 + v * 25]) * (1.f / 8192.f);
        lg[v] = s;
        mx = fmaxf(mx, s);
    }
    float sum = 0.f;
#pragma unroll
    for (int v = 0; v < 25; v++) { lg[v] = expf(lg[v] - mx); sum += lg[v]; }
    float inv = 1.f / sum;
    float* sp = g_S + (n * 3 + i) * 625 + w;
    const float* at = g_Atot + i * 625 + w;
#pragma unroll
    for (int v = 0; v < 25; v++) sp[v * 25] = lg[v] * inv + at[v * 25];
}

// ---------------- xs[n, i*64+c, t, w] = sum_v x[n,c,t,v] * S[n,i,v,w] ------
// 2 c-rows per thread to amortize the broadcast S loads (2 FMA per LDS).
__global__ __launch_bounds__(256) void xs_kernel(const float* __restrict__ x) {
    __shared__ float Ss[1875];
    int tid = threadIdx.x;
    int n = blockIdx.y;
    int cp = blockIdx.x;                 // c = 2*cp, 2*cp+1
    const float* sp = g_S + (long)n * 1875;
    for (int f = tid; f < 1875; f += 256) Ss[f] = sp[f];
    __syncthreads();

    int t = tid;
    const float* x0 = x + (long)n * 409600 + (long)(2 * cp) * TV + t * 25;
    const float* x1 = x0 + TV;
    float xr0[25], xr1[25];
#pragma unroll
    for (int v = 0; v < 25; v++) { xr0[v] = x0[v]; xr1[v] = x1[v]; }

    for (int i = 0; i < 3; i++) {
        const float* si = Ss + i * 625;
        float* op0 = g_ab + (((long)n * 192 + i * 64 + 2 * cp) * 256 + t) * 25;
        float* op1 = op0 + 256L * 25;
        for (int w = 0; w < 25; w++) {
            float s0 = 0.f, s1 = 0.f;
#pragma unroll
            for (int v = 0; v < 25; v++) {
                float sv = si[v * 25 + w];
                s0 = fmaf(xr0[v], sv, s0);
                s1 = fmaf(xr1[v], sv, s1);
            }
            op0[w] = s0;
            op1[w] = s1;
        }
    }
}

// ---------------- BN stats per channel (256 ch over 64*6400 elems) ---------
__global__ __launch_bounds__(256) void stats_kernel(
    const float* __restrict__ gbn, const float* __restrict__ bbn,
    const float* __restrict__ gdn, const float* __restrict__ bdn)
{
    int q = blockIdx.x;
    int tid = threadIdx.x;
    float s = 0.f, s2 = 0.f;
    for (int n = 0; n < NBATCH; n++) {
        const float* zp = g_z + ((long)n * 256 + q) * TV;
        for (int p = tid; p < TV; p += 256) {
            float v = zp[p];
            s += v;
            s2 = fmaf(v, v, s2);
        }
    }
    __shared__ float rs[256], rq[256];
    rs[tid] = s; rq[tid] = s2;
    __syncthreads();
    for (int st = 128; st > 0; st >>= 1) {
        if (tid < st) { rs[tid] += rs[tid + st]; rq[tid] += rq[tid + st]; }
        __syncthreads();
    }
    if (tid == 0) {
        const float inv_m = 1.f / 409600.f;
        float mean = rs[0] * inv_m;
        float var  = rq[0] * inv_m - mean * mean;
        float rinv = rsqrtf(var + 1e-5f);
        float gamma = (q < 128) ? gbn[q] : gdn[q - 128];
        float beta  = (q < 128) ? bbn[q] : bdn[q - 128];
        g_alpha[q] = gamma * rinv;
        g_bet[q]   = beta - mean * gamma * rinv;
    }
}

// ---------------- fused epilogue: out = BN_y(y) + BN_d(down) ---------------
__global__ __launch_bounds__(256) void final_kernel(float* __restrict__ out) {
    int idx = blockIdx.x * 256 + threadIdx.x;       // < 13107200 float4s
    int p4 = idx % 1600;
    int o  = (idx / 1600) & 127;
    int n  = idx / 204800;
    const float4* z4 = (const float4*)g_z;
    long b1 = ((long)n * 256 + o) * 1600 + p4;
    float4 z1 = z4[b1];
    float4 z2 = z4[b1 + 204800];                    // +128 channels
    float a1 = g_alpha[o],       c1 = g_bet[o];
    float a2 = g_alpha[o + 128], c2 = g_bet[o + 128];
    float4 r;
    r.x = fmaf(a1, z1.x, c1) + fmaf(a2, z2.x, c2);
    r.y = fmaf(a1, z1.y, c1) + fmaf(a2, z2.y, c2);
    r.z = fmaf(a1, z1.z, c1) + fmaf(a2, z2.z, c2);
    r.w = fmaf(a1, z1.w, c1) + fmaf(a2, z2.w, c2);
    ((float4*)out)[idx] = r;
}

// ---------------- launcher -------------------------------------------------
extern "C" void kernel_launch(void* const* d_in, const int* in_sizes, int n_in,
                              void* d_out, int out_size) {
    const float* x     = (const float*)d_in[0];
    const float* A     = (const float*)d_in[1];
    const float* PA    = (const float*)d_in[2];
    const float* Wa    = (const float*)d_in[3];
    const float* ba    = (const float*)d_in[4];
    const float* Wb    = (const float*)d_in[5];
    const float* bb    = (const float*)d_in[6];
    const float* Wd    = (const float*)d_in[7];
    const float* bd    = (const float*)d_in[8];
    const float* Wdown = (const float*)d_in[9];
    const float* bdown = (const float*)d_in[10];
    const float* gbn   = (const float*)d_in[11];
    const float* bbn   = (const float*)d_in[12];
    const float* gdn   = (const float*)d_in[13];
    const float* bdn   = (const float*)d_in[14];
    float* out = (float*)d_out;

    prep_kernel<<<48, 256>>>(Wa, ba, Wb, bb, Wd, bd, A, PA);
    gemm_ab<<<dim3(50, 3, 64), 256>>>(x);                 // (192 x 64) @ x
    logits_kernel<<<dim3(3, 64, 4), 256>>>();             // split-K=4
    softmax_kernel<<<19, 256>>>();
    xs_kernel<<<dim3(32, 64), 256>>>(x);                  // S-mix, writes into g_ab
    gemm_y<<<dim3(50, 2, 64), 256>>>();                   // (128 x 192) @ xs
    gemm_down<<<dim3(50, 2, 64), 256>>>(x, Wdown, bdown); // (128 x 64) @ x
    stats_kernel<<<256, 256>>>(gbn, bbn, gdn, bdn);
    final_kernel<<<51200, 256>>>(out);
}

// round 7
// speedup vs baseline: 1.8014x; 1.8014x over previous
#include <cuda_runtime.h>
#include <cuda_bf16.h>
#include <cstdint>

#define TV 6400           // T*V = 256*25
#define NBATCH 64

// ---------------- scratch (device globals; no allocation allowed) ----------
__device__ float g_ab[104857600];   // (64,256,6400): a/b conv out (padded M), REUSED as xs (192-stride)
__device__ float g_z[104857600];    // (64,256,6400): [y | down] pre-BN
__device__ float g_part[480000];    // (4,64,3,625) split-K logits partials
__device__ float g_S[120000];       // (64,3,25,25) final mixing matrix
__device__ float g_Atot[1875];      // A + PA
__device__ float g_by[128];         // sum_i bd[i]
__device__ float g_bab_pad[256];    // [ba|bb|0pad]
__device__ float g_alpha[256];      // BN fused scale
__device__ float g_bet[256];        // BN fused shift
// weights pre-packed in m16n8k16 A-fragment order (hi uint4 then lo uint4 per lane)
__device__ __align__(16) unsigned g_Wabf[16384];  // 16 mb x 4 ks x 32 x 8
__device__ __align__(16) unsigned g_Wyf[24576];   // 8 mb x 12 ks x 32 x 8
__device__ __align__(16) unsigned g_Wdnf[8192];   // 8 mb x 4 ks x 32 x 8

// ---------------- bf16 hi/lo split helpers ---------------------------------
__device__ __forceinline__ unsigned short bf_hi(float v) {
    return __bfloat16_as_ushort(__float2bfloat16(v));
}
__device__ __forceinline__ unsigned short bf_lo(float v) {
    __nv_bfloat16 h = __float2bfloat16(v);
    return __bfloat16_as_ushort(__float2bfloat16(v - __bfloat162float(h)));
}
__device__ __forceinline__ unsigned pack_hi(float v0, float v1) {
    return (unsigned)bf_hi(v0) | ((unsigned)bf_hi(v1) << 16);
}
__device__ __forceinline__ unsigned pack_lo(float v0, float v1) {
    return (unsigned)bf_lo(v0) | ((unsigned)bf_lo(v1) << 16);
}

// ---------------- prep: biases, A+PA, fragment-packed weights --------------
// fragment layout: word index f = (((mb*nK16 + ks)*32 + lane)*8 + r)
//   r 0..3 = a0..a3 hi halves, r 4..7 = a0..a3 lo halves
//   a_rr: row = mb*16 + (lane>>2) + (rr&1)*8 ; col = ks*16 + (lane&3)*2 + (rr&2)*4
__device__ __forceinline__ void frag_decode(int f, int nK16,
                                            int& row, int& col, bool& hi) {
    int r = f & 7, slot = f >> 3;
    int lane = slot & 31, t2 = slot >> 5;
    int ks = t2 % nK16, mb = t2 / nK16;
    int rr = r & 3;
    row = mb * 16 + (lane >> 2) + ((rr & 1) << 3);
    col = ks * 16 + (lane & 3) * 2 + ((rr & 2) << 2);
    hi = r < 4;
}

__global__ __launch_bounds__(256) void prep_kernel(
    const float* __restrict__ Wa, const float* __restrict__ ba,
    const float* __restrict__ Wb, const float* __restrict__ bb,
    const float* __restrict__ Wd, const float* __restrict__ bd,
    const float* __restrict__ Wdown,
    const float* __restrict__ A,  const float* __restrict__ PA)
{
    int stride = gridDim.x * blockDim.x;
    int g = blockIdx.x * blockDim.x + threadIdx.x;
    for (int f = g; f < 256; f += stride)
        g_bab_pad[f] = (f < 96) ? ba[f] : (f < 192 ? bb[f - 96] : 0.f);
    for (int f = g; f < 128; f += stride)
        g_by[f] = bd[f] + bd[128 + f] + bd[256 + f];
    for (int f = g; f < 1875; f += stride)
        g_Atot[f] = A[f] + PA[f];

    // Wab: 256(pad) x 64 ; rows 0..95 = Wa, 96..191 = Wb, rest 0
    for (int f = g; f < 16384; f += stride) {
        int row, col; bool hi;
        frag_decode(f, 4, row, col, hi);
        float v0 = 0.f, v1 = 0.f;
        if (row < 96)       { v0 = Wa[row * 64 + col]; v1 = Wa[row * 64 + col + 1]; }
        else if (row < 192) { v0 = Wb[(row - 96) * 64 + col]; v1 = Wb[(row - 96) * 64 + col + 1]; }
        g_Wabf[f] = hi ? pack_hi(v0, v1) : pack_lo(v0, v1);
    }
    // Wy: 128 x 192 ; W[o][k] = Wd[(i*128+o)*64+c], i=k>>6, c=k&63
    for (int f = g; f < 24576; f += stride) {
        int row, col; bool hi;
        frag_decode(f, 12, row, col, hi);
        int i = col >> 6, c = col & 63;
        float v0 = Wd[(i * 128 + row) * 64 + c];
        float v1 = Wd[(i * 128 + row) * 64 + c + 1];
        g_Wyf[f] = hi ? pack_hi(v0, v1) : pack_lo(v0, v1);
    }
    // Wdown: 128 x 64
    for (int f = g; f < 8192; f += stride) {
        int row, col; bool hi;
        frag_decode(f, 4, row, col, hi);
        float v0 = Wdown[row * 64 + col], v1 = Wdown[row * 64 + col + 1];
        g_Wdnf[f] = hi ? pack_hi(v0, v1) : pack_lo(v0, v1);
    }
}

// ---------------- mma.sync wrapper -----------------------------------------
__device__ __forceinline__ void mma16816(float* c, const uint4& a,
                                         unsigned b0, unsigned b1) {
    asm volatile(
        "mma.sync.aligned.m16n8k16.row.col.f32.bf16.bf16.f32 "
        "{%0,%1,%2,%3}, {%4,%5,%6,%7}, {%8,%9}, {%0,%1,%2,%3};"
        : "+f"(c[0]), "+f"(c[1]), "+f"(c[2]), "+f"(c[3])
        : "r"(a.x), "r"(a.y), "r"(a.z), "r"(a.w), "r"(b0), "r"(b1));
}

// ============== tensor GEMM body: OUT[n,m,p] = sum_k W[m,k] IN[n,k,p]+bias =
// 3-term bf16 emulation (AhBh + AhBl + AlBh) with fp32 register accumulators.
// Block: 128 M x 128 P, K-chunks of 64. 8 warps, warp tile 32M x 64P.
// NOTE: called only from __global__ wrappers so that all device-global
// arrays are referenced from DEVICE code (host cannot take their address).
#define LDB 72   // smem row pitch (144B -> conflict-free fragment LDS)

__device__ __forceinline__ void gemm_body(
    const float* __restrict__ IN, long in_ns,
    const unsigned* __restrict__ Wf, int nK16,
    const float* __restrict__ bias,
    float* __restrict__ OUT, long out_ns, int kchunks)
{
    __shared__ __align__(16) unsigned short Bh[128][LDB];
    __shared__ __align__(16) unsigned short Bl[128][LDB];

    int tid = threadIdx.x, wid = tid >> 5, lane = tid & 31;
    int n = blockIdx.z, pBase = blockIdx.x * 128, mtile = blockIdx.y;
    int warpM = (wid >> 1) * 32, warpP = (wid & 1) * 64;

    float acc[2][8][4];
#pragma unroll
    for (int mi = 0; mi < 2; mi++)
#pragma unroll
        for (int ni = 0; ni < 8; ni++)
#pragma unroll
            for (int r = 0; r < 4; r++) acc[mi][ni][r] = 0.f;

    const float* inp = IN + (long)n * in_ns + pBase;
    int sp = tid & 127;            // staging p
    int skh = (tid >> 7) * 32;     // staging k-half

    for (int kc = 0; kc < kchunks; kc++) {
        __syncthreads();   // prior-iteration LDS done before overwrite
        // ---- stage B: fp32 [k][p] -> bf16 hi/lo [p][k] ----
        const float* colp = inp + (long)(kc * 64 + skh) * TV + sp;
#pragma unroll
        for (int j = 0; j < 32; j += 2) {
            float v0 = colp[(long)j * TV];
            float v1 = colp[(long)(j + 1) * TV];
            *(unsigned*)&Bh[sp][skh + j] = pack_hi(v0, v1);
            *(unsigned*)&Bl[sp][skh + j] = pack_lo(v0, v1);
        }
        __syncthreads();

#pragma unroll
        for (int ks = 0; ks < 4; ks++) {
            int kg = kc * 4 + ks;
            // A fragments from gmem (fragment-packed, L2-resident)
            uint4 Ah[2], Al[2];
#pragma unroll
            for (int mi = 0; mi < 2; mi++) {
                int mb = mtile * 8 + (wid >> 1) * 2 + mi;
                const uint4* fp = (const uint4*)Wf + ((long)(mb * nK16 + kg) * 32 + lane) * 2;
                Ah[mi] = fp[0];
                Al[mi] = fp[1];
            }
            int bk = ks * 16 + (lane & 3) * 2;
#pragma unroll
            for (int ni = 0; ni < 8; ni++) {
                int bp = warpP + ni * 8 + (lane >> 2);
                unsigned bh0 = *(const unsigned*)&Bh[bp][bk];
                unsigned bh1 = *(const unsigned*)&Bh[bp][bk + 8];
                unsigned bl0 = *(const unsigned*)&Bl[bp][bk];
                unsigned bl1 = *(const unsigned*)&Bl[bp][bk + 8];
#pragma unroll
                for (int mi = 0; mi < 2; mi++) {
                    mma16816(acc[mi][ni], Ah[mi], bh0, bh1);
                    mma16816(acc[mi][ni], Ah[mi], bl0, bl1);
                    mma16816(acc[mi][ni], Al[mi], bh0, bh1);
                }
            }
        }
    }

    // ---- epilogue: +bias, float2 stores ----
#pragma unroll
    for (int mi = 0; mi < 2; mi++) {
        int m = mtile * 128 + warpM + mi * 16 + (lane >> 2);
        float b0 = bias[m], b1 = bias[m + 8];
        float* op = OUT + (long)n * out_ns + (long)m * TV + pBase + warpP + (lane & 3) * 2;
#pragma unroll
        for (int ni = 0; ni < 8; ni++) {
            float2 r0 = make_float2(acc[mi][ni][0] + b0, acc[mi][ni][1] + b0);
            float2 r1 = make_float2(acc[mi][ni][2] + b1, acc[mi][ni][3] + b1);
            *(float2*)(op + ni * 8) = r0;
            *(float2*)(op + ni * 8 + 8L * TV) = r1;
        }
    }
}

// ---- wrappers: bind device globals from device code (host can't) ----------
__global__ __launch_bounds__(256, 2) void gemm_ab_k(const float* __restrict__ x) {
    gemm_body(x, 64L * TV, g_Wabf, 4, g_bab_pad, g_ab, 256L * TV, 1);
}
__global__ __launch_bounds__(256, 2) void gemm_y_k() {
    gemm_body(g_ab, 192L * TV, g_Wyf, 12, g_by, g_z, 256L * TV, 3);
}
__global__ __launch_bounds__(256, 2) void gemm_down_k(const float* __restrict__ x,
                                                      const float* __restrict__ bdown) {
    gemm_body(x, 64L * TV, g_Wdnf, 4, bdown, g_z + 128L * TV, 256L * TV, 1);
}

// ---------------- logits: lg[n,i,v,w] = sum_{r,t} a[...v]*b[...w] ----------
// a/b live in g_ab with 256-row batch stride (rows 0..95 = a, 96..191 = b)
__global__ __launch_bounds__(256) void logits_kernel() {
    int i = blockIdx.x, n = blockIdx.y, ks = blockIdx.z;
    __shared__ float As[1600], Bs[1600];
    __shared__ float part[8][625];
    int tid = threadIdx.x;
    int kg = tid >> 5, lane = tid & 31;
    bool active = lane < 25;
    int vb = (lane / 5) * 5, wb = (lane % 5) * 5;
    float acc[5][5];
#pragma unroll
    for (int a = 0; a < 5; a++)
#pragma unroll
        for (int b = 0; b < 5; b++) acc[a][b] = 0.f;

    const float* abase = g_ab + ((long)n * 256 + i * 32) * TV;
    const float* bbase = abase + 96L * TV;

    for (int c = ks * 32; c < ks * 32 + 32; c++) {
        int r = c >> 2, t0 = (c & 3) * 64;
        const float* ap = abase + (long)r * TV + t0 * 25;
        const float* bp = bbase + (long)r * TV + t0 * 25;
        __syncthreads();
        for (int f = tid; f < 1600; f += 256) { As[f] = ap[f]; Bs[f] = bp[f]; }
        __syncthreads();
        if (active) {
#pragma unroll
            for (int kk = 0; kk < 8; kk++) {
                int kb = (kg * 8 + kk) * 25;
                float av[5], bv[5];
#pragma unroll
                for (int a = 0; a < 5; a++) av[a] = As[kb + vb + a];
#pragma unroll
                for (int b = 0; b < 5; b++) bv[b] = Bs[kb + wb + b];
#pragma unroll
                for (int a = 0; a < 5; a++)
#pragma unroll
                    for (int b = 0; b < 5; b++)
                        acc[a][b] = fmaf(av[a], bv[b], acc[a][b]);
            }
        }
    }
    __syncthreads();
    if (active)
#pragma unroll
        for (int a = 0; a < 5; a++)
#pragma unroll
            for (int b = 0; b < 5; b++)
                part[kg][(vb + a) * 25 + wb + b] = acc[a][b];
    __syncthreads();
    float* outp = g_part + ((long)ks * 192 + n * 3 + i) * 625;
    for (int f = tid; f < 625; f += 256) {
        float s = part[0][f] + part[1][f] + part[2][f] + part[3][f]
                + part[4][f] + part[5][f] + part[6][f] + part[7][f];
        outp[f] = s;
    }
}

// ---------------- softmax over v (axis=1) per (n,i,w), + A_tot ------------
__global__ __launch_bounds__(256) void softmax_kernel() {
    int gid = blockIdx.x * blockDim.x + threadIdx.x;
    if (gid >= 64 * 3 * 25) return;
    int w = gid % 25;
    int i = (gid / 25) % 3;
    int n = gid / 75;
    const float* pp = g_part + (n * 3 + i) * 625 + w;
    float lg[25];
    float mx = -1e30f;
#pragma unroll
    for (int v = 0; v < 25; v++) {
        float s = (pp[v * 25] + pp[120000 + v * 25] + pp[240000 + v * 25]
                   + pp[360000 + v * 25]) * (1.f / 8192.f);
        lg[v] = s;
        mx = fmaxf(mx, s);
    }
    float sum = 0.f;
#pragma unroll
    for (int v = 0; v < 25; v++) { lg[v] = expf(lg[v] - mx); sum += lg[v]; }
    float inv = 1.f / sum;
    float* sp = g_S + (n * 3 + i) * 625 + w;
    const float* at = g_Atot + i * 625 + w;
#pragma unroll
    for (int v = 0; v < 25; v++) sp[v * 25] = lg[v] * inv + at[v * 25];
}

// ---------------- xs[n, i*64+c, t, w] = sum_v x[n,c,t,v] * S[n,i,v,w] ------
// writes into g_ab with 192-row batch stride (consumed by gemm_y)
__global__ __launch_bounds__(256) void xs_kernel(const float* __restrict__ x) {
    __shared__ float Ss[1875];
    int tid = threadIdx.x;
    int n = blockIdx.y;
    int cp = blockIdx.x;
    const float* sp = g_S + (long)n * 1875;
    for (int f = tid; f < 1875; f += 256) Ss[f] = sp[f];
    __syncthreads();

    int t = tid;
    const float* x0 = x + (long)n * 409600 + (long)(2 * cp) * TV + t * 25;
    const float* x1 = x0 + TV;
    float xr0[25], xr1[25];
#pragma unroll
    for (int v = 0; v < 25; v++) { xr0[v] = x0[v]; xr1[v] = x1[v]; }

    for (int i = 0; i < 3; i++) {
        const float* si = Ss + i * 625;
        float* op0 = g_ab + (((long)n * 192 + i * 64 + 2 * cp) * 256 + t) * 25;
        float* op1 = op0 + 256L * 25;
        for (int w = 0; w < 25; w++) {
            float s0 = 0.f, s1 = 0.f;
#pragma unroll
            for (int v = 0; v < 25; v++) {
                float sv = si[v * 25 + w];
                s0 = fmaf(xr0[v], sv, s0);
                s1 = fmaf(xr1[v], sv, s1);
            }
            op0[w] = s0;
            op1[w] = s1;
        }
    }
}

// ---------------- BN stats per channel ------------------------------------
__global__ __launch_bounds__(256) void stats_kernel(
    const float* __restrict__ gbn, const float* __restrict__ bbn,
    const float* __restrict__ gdn, const float* __restrict__ bdn)
{
    int q = blockIdx.x;
    int tid = threadIdx.x;
    float s = 0.f, s2 = 0.f;
    for (int n = 0; n < NBATCH; n++) {
        const float* zp = g_z + ((long)n * 256 + q) * TV;
        for (int p = tid; p < TV; p += 256) {
            float v = zp[p];
            s += v;
            s2 = fmaf(v, v, s2);
        }
    }
    __shared__ float rs[256], rq[256];
    rs[tid] = s; rq[tid] = s2;
    __syncthreads();
    for (int st = 128; st > 0; st >>= 1) {
        if (tid < st) { rs[tid] += rs[tid + st]; rq[tid] += rq[tid + st]; }
        __syncthreads();
    }
    if (tid == 0) {
        const float inv_m = 1.f / 409600.f;
        float mean = rs[0] * inv_m;
        float var  = rq[0] * inv_m - mean * mean;
        float rinv = rsqrtf(var + 1e-5f);
        float gamma = (q < 128) ? gbn[q] : gdn[q - 128];
        float beta  = (q < 128) ? bbn[q] : bdn[q - 128];
        g_alpha[q] = gamma * rinv;
        g_bet[q]   = beta - mean * gamma * rinv;
    }
}

// ---------------- fused epilogue: out = BN_y(y) + BN_d(down) ---------------
__global__ __launch_bounds__(256) void final_kernel(float* __restrict__ out) {
    int idx = blockIdx.x * 256 + threadIdx.x;
    int p4 = idx % 1600;
    int o  = (idx / 1600) & 127;
    int n  = idx / 204800;
    const float4* z4 = (const float4*)g_z;
    long b1 = ((long)n * 256 + o) * 1600 + p4;
    float4 z1 = z4[b1];
    float4 z2 = z4[b1 + 204800];
    float a1 = g_alpha[o],       c1 = g_bet[o];
    float a2 = g_alpha[o + 128], c2 = g_bet[o + 128];
    float4 r;
    r.x = fmaf(a1, z1.x, c1) + fmaf(a2, z2.x, c2);
    r.y = fmaf(a1, z1.y, c1) + fmaf(a2, z2.y, c2);
    r.z = fmaf(a1, z1.z, c1) + fmaf(a2, z2.z, c2);
    r.w = fmaf(a1, z1.w, c1) + fmaf(a2, z2.w, c2);
    ((float4*)out)[idx] = r;
}

// ---------------- launcher -------------------------------------------------
extern "C" void kernel_launch(void* const* d_in, const int* in_sizes, int n_in,
                              void* d_out, int out_size) {
    const float* x     = (const float*)d_in[0];
    const float* A     = (const float*)d_in[1];
    const float* PA    = (const float*)d_in[2];
    const float* Wa    = (const float*)d_in[3];
    const float* ba    = (const float*)d_in[4];
    const float* Wb    = (const float*)d_in[5];
    const float* bb    = (const float*)d_in[6];
    const float* Wd    = (const float*)d_in[7];
    const float* bd    = (const float*)d_in[8];
    const float* Wdown = (const float*)d_in[9];
    const float* bdown = (const float*)d_in[10];
    const float* gbn   = (const float*)d_in[11];
    const float* bbn   = (const float*)d_in[12];
    const float* gdn   = (const float*)d_in[13];
    const float* bdn   = (const float*)d_in[14];
    float* out = (float*)d_out;

    prep_kernel<<<48, 256>>>(Wa, ba, Wb, bb, Wd, bd, Wdown, A, PA);

    // conv_a|conv_b: (192x64, M padded to 256) @ x -> g_ab (256-row stride)
    gemm_ab_k<<<dim3(50, 2, 64), 256>>>(x);

    logits_kernel<<<dim3(3, 64, 4), 256>>>();
    softmax_kernel<<<19, 256>>>();
    xs_kernel<<<dim3(32, 64), 256>>>(x);      // overwrites g_ab (192-stride)

    // y = Wd_cat(128x192) @ xs -> g_z[:,0:128]
    gemm_y_k<<<dim3(50, 1, 64), 256>>>();
    // down = Wdown(128x64) @ x -> g_z[:,128:256]
    gemm_down_k<<<dim3(50, 1, 64), 256>>>(x, bdown);

    stats_kernel<<<256, 256>>>(gbn, bbn, gdn, bdn);
    final_kernel<<<51200, 256>>>(out);
}

// round 9
// speedup vs baseline: 2.7369x; 1.5193x over previous
#include <cuda_runtime.h>
#include <cuda_bf16.h>
#include <cstdint>

#define TV 6400           // T*V = 256*25
#define NBATCH 64

// ---------------- scratch (device globals; no allocation allowed) ----------
__device__ __nv_bfloat16 g_abh[104857600]; // (64,256,6400) bf16: a/b conv out (padded M)
__device__ __nv_bfloat16 g_xsb[78643200];  // (64,192,6400) bf16: xs (S-mixed x)
__device__ __nv_bfloat16 g_zy[52428800];   // (64,128,6400) bf16: y pre-BN
__device__ float g_zd[52428800];           // (64,128,6400) fp32: down pre-BN
__device__ float g_part[480000];    // (4,64,3,625) split-K logits partials
__device__ float g_S[120000];       // (64,3,25,25) final mixing matrix
__device__ float g_Atot[1875];      // A + PA
__device__ float g_by[128];         // sum_i bd[i]
__device__ float g_bab_pad[256];    // [ba|bb|0pad]
__device__ float g_alpha[256];      // BN fused scale
__device__ float g_bet[256];        // BN fused shift
__device__ float g_psum[819200];    // (2,64,50,128) per-block channel sums
__device__ float g_psq[819200];     // (2,64,50,128) per-block channel sumsq
// weights pre-packed in m16n8k16 A-fragment order (hi uint4 then lo uint4 per lane)
__device__ __align__(16) unsigned g_Wabf[16384];  // 16 mb x 4 ks x 32 x 8
__device__ __align__(16) unsigned g_Wyf[24576];   // 8 mb x 12 ks x 32 x 8
__device__ __align__(16) unsigned g_Wdnf[8192];   // 8 mb x 4 ks x 32 x 8

// ---------------- bf16 hi/lo split helpers ---------------------------------
__device__ __forceinline__ unsigned short bf_hi(float v) {
    return __bfloat16_as_ushort(__float2bfloat16(v));
}
__device__ __forceinline__ unsigned short bf_lo(float v) {
    __nv_bfloat16 h = __float2bfloat16(v);
    return __bfloat16_as_ushort(__float2bfloat16(v - __bfloat162float(h)));
}
__device__ __forceinline__ unsigned pack_hi(float v0, float v1) {
    return (unsigned)bf_hi(v0) | ((unsigned)bf_hi(v1) << 16);
}
__device__ __forceinline__ unsigned pack_lo(float v0, float v1) {
    return (unsigned)bf_lo(v0) | ((unsigned)bf_lo(v1) << 16);
}

// ---------------- prep: biases, A+PA, fragment-packed weights --------------
__device__ __forceinline__ void frag_decode(int f, int nK16,
                                            int& row, int& col, bool& hi) {
    int r = f & 7, slot = f >> 3;
    int lane = slot & 31, t2 = slot >> 5;
    int ks = t2 % nK16, mb = t2 / nK16;
    int rr = r & 3;
    row = mb * 16 + (lane >> 2) + ((rr & 1) << 3);
    col = ks * 16 + (lane & 3) * 2 + ((rr & 2) << 2);
    hi = r < 4;
}

__global__ __launch_bounds__(256) void prep_kernel(
    const float* __restrict__ Wa, const float* __restrict__ ba,
    const float* __restrict__ Wb, const float* __restrict__ bb,
    const float* __restrict__ Wd, const float* __restrict__ bd,
    const float* __restrict__ Wdown,
    const float* __restrict__ A,  const float* __restrict__ PA)
{
    int stride = gridDim.x * blockDim.x;
    int g = blockIdx.x * blockDim.x + threadIdx.x;
    for (int f = g; f < 256; f += stride)
        g_bab_pad[f] = (f < 96) ? ba[f] : (f < 192 ? bb[f - 96] : 0.f);
    for (int f = g; f < 128; f += stride)
        g_by[f] = bd[f] + bd[128 + f] + bd[256 + f];
    for (int f = g; f < 1875; f += stride)
        g_Atot[f] = A[f] + PA[f];

    for (int f = g; f < 16384; f += stride) {
        int row, col; bool hi;
        frag_decode(f, 4, row, col, hi);
        float v0 = 0.f, v1 = 0.f;
        if (row < 96)       { v0 = Wa[row * 64 + col]; v1 = Wa[row * 64 + col + 1]; }
        else if (row < 192) { v0 = Wb[(row - 96) * 64 + col]; v1 = Wb[(row - 96) * 64 + col + 1]; }
        g_Wabf[f] = hi ? pack_hi(v0, v1) : pack_lo(v0, v1);
    }
    for (int f = g; f < 24576; f += stride) {
        int row, col; bool hi;
        frag_decode(f, 12, row, col, hi);
        int i = col >> 6, c = col & 63;
        float v0 = Wd[(i * 128 + row) * 64 + c];
        float v1 = Wd[(i * 128 + row) * 64 + c + 1];
        g_Wyf[f] = hi ? pack_hi(v0, v1) : pack_lo(v0, v1);
    }
    for (int f = g; f < 8192; f += stride) {
        int row, col; bool hi;
        frag_decode(f, 4, row, col, hi);
        float v0 = Wdown[row * 64 + col], v1 = Wdown[row * 64 + col + 1];
        g_Wdnf[f] = hi ? pack_hi(v0, v1) : pack_lo(v0, v1);
    }
}

// ---------------- mma.sync wrapper -----------------------------------------
__device__ __forceinline__ void mma16816(float* c, const uint4& a,
                                         unsigned b0, unsigned b1) {
    asm volatile(
        "mma.sync.aligned.m16n8k16.row.col.f32.bf16.bf16.f32 "
        "{%0,%1,%2,%3}, {%4,%5,%6,%7}, {%8,%9}, {%0,%1,%2,%3};"
        : "+f"(c[0]), "+f"(c[1]), "+f"(c[2]), "+f"(c[3])
        : "r"(a.x), "r"(a.y), "r"(a.z), "r"(a.w), "r"(b0), "r"(b1));
}

#define LDB 72   // smem row pitch (144B -> conflict-free fragment LDS)

// =============== GEMM 1: a/b conv, single-term bf16, bf16 out ==============
// grid (50, 2, 64); block 256. OUT rows padded to 256.
__global__ __launch_bounds__(256, 2) void gemm_ab_k(const float* __restrict__ x) {
    __shared__ __align__(16) unsigned short Bh[128][LDB];
    int tid = threadIdx.x, wid = tid >> 5, lane = tid & 31;
    int n = blockIdx.z, pBase = blockIdx.x * 128, mtile = blockIdx.y;
    int warpM = (wid >> 1) * 32, warpP = (wid & 1) * 64;
    float acc[2][8][4] = {};

    const float* inp = x + (long)n * (64L * TV) + pBase;
    int sp = tid & 127, skh = (tid >> 7) * 32;
    const float* colp = inp + (long)skh * TV + sp;
#pragma unroll
    for (int j = 0; j < 32; j += 2) {
        float v0 = colp[(long)j * TV];
        float v1 = colp[(long)(j + 1) * TV];
        *(unsigned*)&Bh[sp][skh + j] = pack_hi(v0, v1);
    }
    __syncthreads();

#pragma unroll
    for (int ks = 0; ks < 4; ks++) {
        uint4 Ah[2];
#pragma unroll
        for (int mi = 0; mi < 2; mi++) {
            int mb = mtile * 8 + (wid >> 1) * 2 + mi;
            const uint4* fp = (const uint4*)g_Wabf + ((long)(mb * 4 + ks) * 32 + lane) * 2;
            Ah[mi] = fp[0];
        }
        int bk = ks * 16 + (lane & 3) * 2;
#pragma unroll
        for (int ni = 0; ni < 8; ni++) {
            int bp = warpP + ni * 8 + (lane >> 2);
            unsigned bh0 = *(const unsigned*)&Bh[bp][bk];
            unsigned bh1 = *(const unsigned*)&Bh[bp][bk + 8];
#pragma unroll
            for (int mi = 0; mi < 2; mi++)
                mma16816(acc[mi][ni], Ah[mi], bh0, bh1);
        }
    }

#pragma unroll
    for (int mi = 0; mi < 2; mi++) {
        int m = mtile * 128 + warpM + mi * 16 + (lane >> 2);
        float b0 = g_bab_pad[m], b1 = g_bab_pad[m + 8];
        __nv_bfloat16* op = g_abh + ((long)n * 256 + m) * TV + pBase + warpP + (lane & 3) * 2;
#pragma unroll
        for (int ni = 0; ni < 8; ni++) {
            __nv_bfloat162 p0, p1;
            p0.x = __float2bfloat16(acc[mi][ni][0] + b0);
            p0.y = __float2bfloat16(acc[mi][ni][1] + b0);
            p1.x = __float2bfloat16(acc[mi][ni][2] + b1);
            p1.y = __float2bfloat16(acc[mi][ni][3] + b1);
            *(__nv_bfloat162*)(op + ni * 8) = p0;
            *(__nv_bfloat162*)(op + ni * 8 + 8L * TV) = p1;
        }
    }
}

// =============== GEMM 2: y = Wd_cat @ xs, bf16 in/out, + stats =============
// grid (50, 1, 64)
__global__ __launch_bounds__(256, 2) void gemm_y_k() {
    __shared__ __align__(16) unsigned short Bh[128][LDB];
    __shared__ float redS[8][8][4], redQ[8][8][4];
    int tid = threadIdx.x, wid = tid >> 5, lane = tid & 31;
    int n = blockIdx.z, pBase = blockIdx.x * 128;
    int warpM = (wid >> 1) * 32, warpP = (wid & 1) * 64;
    float acc[2][8][4] = {};

    const __nv_bfloat16* inb = g_xsb + (long)n * (192L * TV) + pBase;
    int pq = tid & 63, skq = (tid >> 6) * 16;

    for (int kc = 0; kc < 3; kc++) {
        __syncthreads();
        const __nv_bfloat16* colb = inb + (long)(kc * 64 + skq) * TV + pq * 2;
#pragma unroll
        for (int j = 0; j < 16; j++) {
            __nv_bfloat162 v = *(const __nv_bfloat162*)(colb + (long)j * TV);
            Bh[pq * 2][skq + j]     = __bfloat16_as_ushort(v.x);
            Bh[pq * 2 + 1][skq + j] = __bfloat16_as_ushort(v.y);
        }
        __syncthreads();
#pragma unroll
        for (int ks = 0; ks < 4; ks++) {
            int kg = kc * 4 + ks;
            uint4 Ah[2];
#pragma unroll
            for (int mi = 0; mi < 2; mi++) {
                int mb = (wid >> 1) * 2 + mi;
                const uint4* fp = (const uint4*)g_Wyf + ((long)(mb * 12 + kg) * 32 + lane) * 2;
                Ah[mi] = fp[0];
            }
            int bk = ks * 16 + (lane & 3) * 2;
#pragma unroll
            for (int ni = 0; ni < 8; ni++) {
                int bp = warpP + ni * 8 + (lane >> 2);
                unsigned bh0 = *(const unsigned*)&Bh[bp][bk];
                unsigned bh1 = *(const unsigned*)&Bh[bp][bk + 8];
#pragma unroll
                for (int mi = 0; mi < 2; mi++)
                    mma16816(acc[mi][ni], Ah[mi], bh0, bh1);
            }
        }
    }

    float ssum[2][2] = {}, ssq[2][2] = {};
#pragma unroll
    for (int mi = 0; mi < 2; mi++) {
        int m = warpM + mi * 16 + (lane >> 2);
        float b0 = g_by[m], b1 = g_by[m + 8];
        __nv_bfloat16* op = g_zy + ((long)n * 128 + m) * TV + pBase + warpP + (lane & 3) * 2;
#pragma unroll
        for (int ni = 0; ni < 8; ni++) {
            float v0 = acc[mi][ni][0] + b0, v1 = acc[mi][ni][1] + b0;
            float v2 = acc[mi][ni][2] + b1, v3 = acc[mi][ni][3] + b1;
            __nv_bfloat162 p0, p1;
            p0.x = __float2bfloat16(v0); p0.y = __float2bfloat16(v1);
            p1.x = __float2bfloat16(v2); p1.y = __float2bfloat16(v3);
            *(__nv_bfloat162*)(op + ni * 8) = p0;
            *(__nv_bfloat162*)(op + ni * 8 + 8L * TV) = p1;
            ssum[mi][0] += v0 + v1; ssq[mi][0] += v0 * v0 + v1 * v1;
            ssum[mi][1] += v2 + v3; ssq[mi][1] += v2 * v2 + v3 * v3;
        }
    }
#pragma unroll
    for (int mi = 0; mi < 2; mi++)
#pragma unroll
        for (int hi = 0; hi < 2; hi++) {
            float s = ssum[mi][hi], q = ssq[mi][hi];
            s += __shfl_xor_sync(0xffffffffu, s, 1);
            s += __shfl_xor_sync(0xffffffffu, s, 2);
            q += __shfl_xor_sync(0xffffffffu, q, 1);
            q += __shfl_xor_sync(0xffffffffu, q, 2);
            if ((lane & 3) == 0) {
                redS[wid][lane >> 2][mi * 2 + hi] = s;
                redQ[wid][lane >> 2][mi * 2 + hi] = q;
            }
        }
    __syncthreads();
    if (tid < 128) {
        int r = tid, mt = r >> 5, rr = r & 31;
        int mi = rr >> 4, hi = (rr >> 3) & 1, q8 = rr & 7;
        int w0 = mt * 2;
        float S = redS[w0][q8][mi * 2 + hi] + redS[w0 + 1][q8][mi * 2 + hi];
        float Q = redQ[w0][q8][mi * 2 + hi] + redQ[w0 + 1][q8][mi * 2 + hi];
        long idx = ((long)n * 50 + blockIdx.x) * 128 + r;
        g_psum[idx] = S;
        g_psq[idx] = Q;
    }
}

// =============== GEMM 3: down = Wdown @ x, 3-term, fp32 out, + stats =======
// grid (50, 1, 64)
__global__ __launch_bounds__(256, 2) void gemm_down_k(const float* __restrict__ x,
                                                      const float* __restrict__ bdown) {
    __shared__ __align__(16) unsigned short Bh[128][LDB];
    __shared__ __align__(16) unsigned short Bl[128][LDB];
    __shared__ float redS[8][8][4], redQ[8][8][4];
    int tid = threadIdx.x, wid = tid >> 5, lane = tid & 31;
    int n = blockIdx.z, pBase = blockIdx.x * 128;
    int warpM = (wid >> 1) * 32, warpP = (wid & 1) * 64;
    float acc[2][8][4] = {};

    const float* inp = x + (long)n * (64L * TV) + pBase;
    int sp = tid & 127, skh = (tid >> 7) * 32;
    const float* colp = inp + (long)skh * TV + sp;
#pragma unroll
    for (int j = 0; j < 32; j += 2) {
        float v0 = colp[(long)j * TV];
        float v1 = colp[(long)(j + 1) * TV];
        *(unsigned*)&Bh[sp][skh + j] = pack_hi(v0, v1);
        *(unsigned*)&Bl[sp][skh + j] = pack_lo(v0, v1);
    }
    __syncthreads();

#pragma unroll
    for (int ks = 0; ks < 4; ks++) {
        uint4 Ah[2], Al[2];
#pragma unroll
        for (int mi = 0; mi < 2; mi++) {
            int mb = (wid >> 1) * 2 + mi;
            const uint4* fp = (const uint4*)g_Wdnf + ((long)(mb * 4 + ks) * 32 + lane) * 2;
            Ah[mi] = fp[0];
            Al[mi] = fp[1];
        }
        int bk = ks * 16 + (lane & 3) * 2;
#pragma unroll
        for (int ni = 0; ni < 8; ni++) {
            int bp = warpP + ni * 8 + (lane >> 2);
            unsigned bh0 = *(const unsigned*)&Bh[bp][bk];
            unsigned bh1 = *(const unsigned*)&Bh[bp][bk + 8];
            unsigned bl0 = *(const unsigned*)&Bl[bp][bk];
            unsigned bl1 = *(const unsigned*)&Bl[bp][bk + 8];
#pragma unroll
            for (int mi = 0; mi < 2; mi++) {
                mma16816(acc[mi][ni], Ah[mi], bh0, bh1);
                mma16816(acc[mi][ni], Ah[mi], bl0, bl1);
                mma16816(acc[mi][ni], Al[mi], bh0, bh1);
            }
        }
    }

    float ssum[2][2] = {}, ssq[2][2] = {};
#pragma unroll
    for (int mi = 0; mi < 2; mi++) {
        int m = warpM + mi * 16 + (lane >> 2);
        float b0 = bdown[m], b1 = bdown[m + 8];
        float* op = g_zd + ((long)n * 128 + m) * TV + pBase + warpP + (lane & 3) * 2;
#pragma unroll
        for (int ni = 0; ni < 8; ni++) {
            float v0 = acc[mi][ni][0] + b0, v1 = acc[mi][ni][1] + b0;
            float v2 = acc[mi][ni][2] + b1, v3 = acc[mi][ni][3] + b1;
            *(float2*)(op + ni * 8) = make_float2(v0, v1);
            *(float2*)(op + ni * 8 + 8L * TV) = make_float2(v2, v3);
            ssum[mi][0] += v0 + v1; ssq[mi][0] += v0 * v0 + v1 * v1;
            ssum[mi][1] += v2 + v3; ssq[mi][1] += v2 * v2 + v3 * v3;
        }
    }
#pragma unroll
    for (int mi = 0; mi < 2; mi++)
#pragma unroll
        for (int hi = 0; hi < 2; hi++) {
            float s = ssum[mi][hi], q = ssq[mi][hi];
            s += __shfl_xor_sync(0xffffffffu, s, 1);
            s += __shfl_xor_sync(0xffffffffu, s, 2);
            q += __shfl_xor_sync(0xffffffffu, q, 1);
            q += __shfl_xor_sync(0xffffffffu, q, 2);
            if ((lane & 3) == 0) {
                redS[wid][lane >> 2][mi * 2 + hi] = s;
                redQ[wid][lane >> 2][mi * 2 + hi] = q;
            }
        }
    __syncthreads();
    if (tid < 128) {
        int r = tid, mt = r >> 5, rr = r & 31;
        int mi = rr >> 4, hi = (rr >> 3) & 1, q8 = rr & 7;
        int w0 = mt * 2;
        float S = redS[w0][q8][mi * 2 + hi] + redS[w0 + 1][q8][mi * 2 + hi];
        float Q = redQ[w0][q8][mi * 2 + hi] + redQ[w0 + 1][q8][mi * 2 + hi];
        long idx = (((long)64 + n) * 50 + blockIdx.x) * 128 + r;
        g_psum[idx] = S;
        g_psq[idx] = Q;
    }
}

// ---------------- logits: lg[n,i,v,w] = sum_{r,t} a[...v]*b[...w] ----------
// a/b in bf16 g_abh (256-row stride: rows 0..95 = a, 96..191 = b)
__global__ __launch_bounds__(256) void logits_kernel() {
    int i = blockIdx.x, n = blockIdx.y, ks = blockIdx.z;
    __shared__ float As[1600], Bs[1600];
    __shared__ float part[8][625];
    int tid = threadIdx.x;
    int kg = tid >> 5, lane = tid & 31;
    bool active = lane < 25;
    int vb = (lane / 5) * 5, wb = (lane % 5) * 5;
    float acc[5][5];
#pragma unroll
    for (int a = 0; a < 5; a++)
#pragma unroll
        for (int b = 0; b < 5; b++) acc[a][b] = 0.f;

    const __nv_bfloat16* abase = g_abh + ((long)n * 256 + i * 32) * TV;
    const __nv_bfloat16* bbase = abase + 96L * TV;

    for (int c = ks * 32; c < ks * 32 + 32; c++) {
        int r = c >> 2, t0 = (c & 3) * 64;
        const __nv_bfloat16* ap = abase + (long)r * TV + t0 * 25;
        const __nv_bfloat16* bp = bbase + (long)r * TV + t0 * 25;
        __syncthreads();
        for (int f = tid; f < 800; f += 256) {
            __nv_bfloat162 va = ((const __nv_bfloat162*)ap)[f];
            __nv_bfloat162 vb2 = ((const __nv_bfloat162*)bp)[f];
            As[2 * f] = __bfloat162float(va.x);  As[2 * f + 1] = __bfloat162float(va.y);
            Bs[2 * f] = __bfloat162float(vb2.x); Bs[2 * f + 1] = __bfloat162float(vb2.y);
        }
        __syncthreads();
        if (active) {
#pragma unroll
            for (int kk = 0; kk < 8; kk++) {
                int kb = (kg * 8 + kk) * 25;
                float av[5], bv[5];
#pragma unroll
                for (int a = 0; a < 5; a++) av[a] = As[kb + vb + a];
#pragma unroll
                for (int b = 0; b < 5; b++) bv[b] = Bs[kb + wb + b];
#pragma unroll
                for (int a = 0; a < 5; a++)
#pragma unroll
                    for (int b = 0; b < 5; b++)
                        acc[a][b] = fmaf(av[a], bv[b], acc[a][b]);
            }
        }
    }
    __syncthreads();
    if (active)
#pragma unroll
        for (int a = 0; a < 5; a++)
#pragma unroll
            for (int b = 0; b < 5; b++)
                part[kg][(vb + a) * 25 + wb + b] = acc[a][b];
    __syncthreads();
    float* outp = g_part + ((long)ks * 192 + n * 3 + i) * 625;
    for (int f = tid; f < 625; f += 256) {
        float s = part[0][f] + part[1][f] + part[2][f] + part[3][f]
                + part[4][f] + part[5][f] + part[6][f] + part[7][f];
        outp[f] = s;
    }
}

// ---------------- softmax over v (axis=1) per (n,i,w), + A_tot ------------
__global__ __launch_bounds__(256) void softmax_kernel() {
    int gid = blockIdx.x * blockDim.x + threadIdx.x;
    if (gid >= 64 * 3 * 25) return;
    int w = gid % 25;
    int i = (gid / 25) % 3;
    int n = gid / 75;
    const float* pp = g_part + (n * 3 + i) * 625 + w;
    float lg[25];
    float mx = -1e30f;
#pragma unroll
    for (int v = 0; v < 25; v++) {
        float s = (pp[v * 25] + pp[120000 + v * 25] + pp[240000 + v * 25]
                   + pp[360000 + v * 25]) * (1.f / 8192.f);
        lg[v] = s;
        mx = fmaxf(mx, s);
    }
    float sum = 0.f;
#pragma unroll
    for (int v = 0; v < 25; v++) { lg[v] = expf(lg[v] - mx); sum += lg[v]; }
    float inv = 1.f / sum;
    float* sp = g_S + (n * 3 + i) * 625 + w;
    const float* at = g_Atot + i * 625 + w;
#pragma unroll
    for (int v = 0; v < 25; v++) sp[v * 25] = lg[v] * inv + at[v * 25];
}

// ---------------- xs[n, i*64+c, t, w] = sum_v x[n,c,t,v] * S[n,i,v,w] ------
// smem-tiled: coalesced gmem I/O, conflict-free LDS, bf16 output to g_xsb.
__global__ __launch_bounds__(256) void xs_kernel(const float* __restrict__ x) {
    __shared__ float Ss[1875];
    __shared__ float xt[2][800];   // [c][tl*25+v], 32 t per chunk
    __shared__ float ot[2][800];   // [c][tl*25+w]
    int tid = threadIdx.x, wid = tid >> 5, lane = tid & 31;
    int n = blockIdx.y, cp = blockIdx.x;
    const float* spt = g_S + (long)n * 1875;
    for (int f = tid; f < 1875; f += 256) Ss[f] = spt[f];

    int c = wid >> 2;       // 0/1 : channel within pair
    int wq = wid & 3;       // w stride class
    const float* xb = x + (long)n * 409600 + (long)(2 * cp) * TV;

    for (int tch = 0; tch < 8; tch++) {
        __syncthreads();
        for (int f = tid; f < 1600; f += 256) {
            int cc = f / 800, j = f - cc * 800;
            xt[cc][j] = xb[(long)cc * TV + tch * 800 + j];
        }
        __syncthreads();
        float xr[25];
#pragma unroll
        for (int v = 0; v < 25; v++) xr[v] = xt[c][lane * 25 + v];

        for (int i = 0; i < 3; i++) {
            for (int w = wq; w < 25; w += 4) {
                float s = 0.f;
#pragma unroll
                for (int v = 0; v < 25; v++)
                    s = fmaf(xr[v], Ss[i * 625 + v * 25 + w], s);
                ot[c][lane * 25 + w] = s;
            }
            __syncthreads();
            __nv_bfloat16* op = g_xsb + ((long)n * 192 + i * 64 + 2 * cp) * TV + tch * 800;
            for (int f = tid; f < 800; f += 256) {
                int cc = f / 400, j = f - cc * 400;
                __nv_bfloat162 pk;
                pk.x = __float2bfloat16(ot[cc][2 * j]);
                pk.y = __float2bfloat16(ot[cc][2 * j + 1]);
                *(__nv_bfloat162*)(op + (long)cc * TV + 2 * j) = pk;
            }
            __syncthreads();
        }
    }
}

// ---------------- stats reduce: per-channel mean/var from block partials ---
__global__ __launch_bounds__(256) void stats_reduce(
    const float* __restrict__ gbn, const float* __restrict__ bbn,
    const float* __restrict__ gdn, const float* __restrict__ bdn)
{
    int qch = blockIdx.x;            // 0..255 ; <128 = y, >=128 = down
    int half = qch >> 7, r = qch & 127;
    int tid = threadIdx.x;
    float s = 0.f, q = 0.f;
    for (int f = tid; f < 3200; f += 256) {
        long idx = (((long)half * 64 + f / 50) * 50 + (f % 50)) * 128 + r;
        s += g_psum[idx];
        q += g_psq[idx];
    }
    __shared__ float rs[256], rq[256];
    rs[tid] = s; rq[tid] = q;
    __syncthreads();
    for (int st = 128; st > 0; st >>= 1) {
        if (tid < st) { rs[tid] += rs[tid + st]; rq[tid] += rq[tid + st]; }
        __syncthreads();
    }
    if (tid == 0) {
        const float inv_m = 1.f / 409600.f;
        float mean = rs[0] * inv_m;
        float var  = rq[0] * inv_m - mean * mean;
        float rinv = rsqrtf(var + 1e-5f);
        float gamma = half ? gdn[r] : gbn[r];
        float beta  = half ? bdn[r] : bbn[r];
        g_alpha[qch] = gamma * rinv;
        g_bet[qch]   = beta - mean * gamma * rinv;
    }
}

// ---------------- fused epilogue: out = BN_y(y) + BN_d(down) ---------------
__global__ __launch_bounds__(256) void final_kernel(float* __restrict__ out) {
    int idx = blockIdx.x * 256 + threadIdx.x;
    int p4 = idx % 1600;
    int o  = (idx / 1600) & 127;
    int n  = idx / 204800;
    long e = ((long)n * 128 + o) * TV + p4 * 4;
    uint2 yb = *(const uint2*)(g_zy + e);
    __nv_bfloat162 y01 = *(__nv_bfloat162*)&yb.x;
    __nv_bfloat162 y23 = *(__nv_bfloat162*)&yb.y;
    float4 zd = *(const float4*)(g_zd + e);
    float a1 = g_alpha[o],       c1 = g_bet[o];
    float a2 = g_alpha[o + 128], c2 = g_bet[o + 128];
    float4 r;
    r.x = fmaf(a1, __bfloat162float(y01.x), c1) + fmaf(a2, zd.x, c2);
    r.y = fmaf(a1, __bfloat162float(y01.y), c1) + fmaf(a2, zd.y, c2);
    r.z = fmaf(a1, __bfloat162float(y23.x), c1) + fmaf(a2, zd.z, c2);
    r.w = fmaf(a1, __bfloat162float(y23.y), c1) + fmaf(a2, zd.w, c2);
    ((float4*)out)[idx] = r;
}

// ---------------- launcher -------------------------------------------------
extern "C" void kernel_launch(void* const* d_in, const int* in_sizes, int n_in,
                              void* d_out, int out_size) {
    const float* x     = (const float*)d_in[0];
    const float* A     = (const float*)d_in[1];
    const float* PA    = (const float*)d_in[2];
    const float* Wa    = (const float*)d_in[3];
    const float* ba    = (const float*)d_in[4];
    const float* Wb    = (const float*)d_in[5];
    const float* bb    = (const float*)d_in[6];
    const float* Wd    = (const float*)d_in[7];
    const float* bd    = (const float*)d_in[8];
    const float* Wdown = (const float*)d_in[9];
    const float* bdown = (const float*)d_in[10];
    const float* gbn   = (const float*)d_in[11];
    const float* bbn   = (const float*)d_in[12];
    const float* gdn   = (const float*)d_in[13];
    const float* bdn   = (const float*)d_in[14];
    float* out = (float*)d_out;

    prep_kernel<<<48, 256>>>(Wa, ba, Wb, bb, Wd, bd, Wdown, A, PA);

    gemm_ab_k<<<dim3(50, 2, 64), 256>>>(x);       // a|b -> g_abh (bf16)
    logits_kernel<<<dim3(3, 64, 4), 256>>>();
    softmax_kernel<<<19, 256>>>();
    xs_kernel<<<dim3(32, 64), 256>>>(x);          // xs -> g_xsb (bf16)

    gemm_y_k<<<dim3(50, 1, 64), 256>>>();         // y -> g_zy (bf16) + stats partials
    gemm_down_k<<<dim3(50, 1, 64), 256>>>(x, bdown); // down -> g_zd (fp32) + stats partials

    stats_reduce<<<256, 256>>>(gbn, bbn, gdn, bdn);
    final_kernel<<<51200, 256>>>(out);
}

// round 10
// speedup vs baseline: 3.3041x; 1.2072x over previous
#include <cuda_runtime.h>
#include <cuda_bf16.h>
#include <cstdint>

#define TV 6400           // T*V = 256*25
#define NBATCH 64

// ---------------- scratch (device globals; no allocation allowed) ----------
__device__ __nv_bfloat16 g_abh[104857600]; // (64,256,6400) bf16: a/b conv out (rows 0..191 used)
__device__ __nv_bfloat16 g_xsb[78643200];  // (64,192,6400) bf16: xs (S-mixed x)
__device__ __nv_bfloat16 g_zy[52428800];   // (64,128,6400) bf16: y pre-BN
__device__ float g_zd[52428800];           // (64,128,6400) fp32: down pre-BN
__device__ float g_part[480000];    // (4,64,3,625) split-K logits partials
__device__ float g_S[120000];       // (64,3,25,25) final mixing matrix
__device__ float g_Atot[1875];      // A + PA
__device__ float g_by[128];         // sum_i bd[i]
__device__ float g_bab_pad[256];    // [ba|bb|0pad]
__device__ float g_alpha[256];      // BN fused scale
__device__ float g_bet[256];        // BN fused shift
__device__ float g_psum[819200];    // (2,64,50,128) per-block channel sums
__device__ float g_psq[819200];     // (2,64,50,128) per-block channel sumsq
// weights pre-packed in m16n8k16 A-fragment order (hi uint4 then lo uint4 per lane)
__device__ __align__(16) unsigned g_Wabf[16384];  // 16 mb x 4 ks x 32 x 8
__device__ __align__(16) unsigned g_Wyf[24576];   // 8 mb x 12 ks x 32 x 8
__device__ __align__(16) unsigned g_Wdnf[8192];   // 8 mb x 4 ks x 32 x 8

// ---------------- bf16 hi/lo split helpers ---------------------------------
__device__ __forceinline__ unsigned short bf_hi(float v) {
    return __bfloat16_as_ushort(__float2bfloat16(v));
}
__device__ __forceinline__ unsigned short bf_lo(float v) {
    __nv_bfloat16 h = __float2bfloat16(v);
    return __bfloat16_as_ushort(__float2bfloat16(v - __bfloat162float(h)));
}
__device__ __forceinline__ unsigned pack_hi(float v0, float v1) {
    return (unsigned)bf_hi(v0) | ((unsigned)bf_hi(v1) << 16);
}
__device__ __forceinline__ unsigned pack_lo(float v0, float v1) {
    return (unsigned)bf_lo(v0) | ((unsigned)bf_lo(v1) << 16);
}

// ---------------- prep: biases, A+PA, fragment-packed weights --------------
__device__ __forceinline__ void frag_decode(int f, int nK16,
                                            int& row, int& col, bool& hi) {
    int r = f & 7, slot = f >> 3;
    int lane = slot & 31, t2 = slot >> 5;
    int ks = t2 % nK16, mb = t2 / nK16;
    int rr = r & 3;
    row = mb * 16 + (lane >> 2) + ((rr & 1) << 3);
    col = ks * 16 + (lane & 3) * 2 + ((rr & 2) << 2);
    hi = r < 4;
}

__global__ __launch_bounds__(256) void prep_kernel(
    const float* __restrict__ Wa, const float* __restrict__ ba,
    const float* __restrict__ Wb, const float* __restrict__ bb,
    const float* __restrict__ Wd, const float* __restrict__ bd,
    const float* __restrict__ Wdown,
    const float* __restrict__ A,  const float* __restrict__ PA)
{
    int stride = gridDim.x * blockDim.x;
    int g = blockIdx.x * blockDim.x + threadIdx.x;
    for (int f = g; f < 256; f += stride)
        g_bab_pad[f] = (f < 96) ? ba[f] : (f < 192 ? bb[f - 96] : 0.f);
    for (int f = g; f < 128; f += stride)
        g_by[f] = bd[f] + bd[128 + f] + bd[256 + f];
    for (int f = g; f < 1875; f += stride)
        g_Atot[f] = A[f] + PA[f];

    for (int f = g; f < 16384; f += stride) {
        int row, col; bool hi;
        frag_decode(f, 4, row, col, hi);
        float v0 = 0.f, v1 = 0.f;
        if (row < 96)       { v0 = Wa[row * 64 + col]; v1 = Wa[row * 64 + col + 1]; }
        else if (row < 192) { v0 = Wb[(row - 96) * 64 + col]; v1 = Wb[(row - 96) * 64 + col + 1]; }
        g_Wabf[f] = hi ? pack_hi(v0, v1) : pack_lo(v0, v1);
    }
    for (int f = g; f < 24576; f += stride) {
        int row, col; bool hi;
        frag_decode(f, 12, row, col, hi);
        int i = col >> 6, c = col & 63;
        float v0 = Wd[(i * 128 + row) * 64 + c];
        float v1 = Wd[(i * 128 + row) * 64 + c + 1];
        g_Wyf[f] = hi ? pack_hi(v0, v1) : pack_lo(v0, v1);
    }
    for (int f = g; f < 8192; f += stride) {
        int row, col; bool hi;
        frag_decode(f, 4, row, col, hi);
        float v0 = Wdown[row * 64 + col], v1 = Wdown[row * 64 + col + 1];
        g_Wdnf[f] = hi ? pack_hi(v0, v1) : pack_lo(v0, v1);
    }
}

// ---------------- mma.sync wrapper -----------------------------------------
__device__ __forceinline__ void mma16816(float* c, const uint4& a,
                                         unsigned b0, unsigned b1) {
    asm volatile(
        "mma.sync.aligned.m16n8k16.row.col.f32.bf16.bf16.f32 "
        "{%0,%1,%2,%3}, {%4,%5,%6,%7}, {%8,%9}, {%0,%1,%2,%3};"
        : "+f"(c[0]), "+f"(c[1]), "+f"(c[2]), "+f"(c[3])
        : "r"(a.x), "r"(a.y), "r"(a.z), "r"(a.w), "r"(b0), "r"(b1));
}

#define LDB 72   // smem row pitch (144B -> conflict-free fragment LDS)

// ========== fused GEMM: ab (mtile 0,1) + down (mtile 2); shares x read =====
// grid (50, 3, 64); block 256.
__global__ __launch_bounds__(256, 2) void gemm_abdn_k(const float* __restrict__ x,
                                                      const float* __restrict__ bdown) {
    __shared__ __align__(16) unsigned short Bh[128][LDB];
    __shared__ __align__(16) unsigned short Bl[128][LDB];
    __shared__ float redS[8][8][4], redQ[8][8][4];
    int tid = threadIdx.x, wid = tid >> 5, lane = tid & 31;
    int n = blockIdx.z, pBase = blockIdx.x * 128, mtile = blockIdx.y;
    int warpM = (wid >> 1) * 32, warpP = (wid & 1) * 64;
    float acc[2][8][4] = {};

    const float* inp = x + (long)n * (64L * TV) + pBase;
    int sp = tid & 127, skh = (tid >> 7) * 32;
    const float* colp = inp + (long)skh * TV + sp;
#pragma unroll
    for (int j = 0; j < 32; j += 2) {
        float v0 = colp[(long)j * TV];
        float v1 = colp[(long)(j + 1) * TV];
        *(unsigned*)&Bh[sp][skh + j] = pack_hi(v0, v1);
        *(unsigned*)&Bl[sp][skh + j] = pack_lo(v0, v1);
    }
    __syncthreads();

    if (mtile < 2) {
        // ---------- ab path: single-term bf16, bf16 out, rows < 192 --------
#pragma unroll
        for (int ks = 0; ks < 4; ks++) {
            uint4 Ah[2];
#pragma unroll
            for (int mi = 0; mi < 2; mi++) {
                int mb = mtile * 8 + (wid >> 1) * 2 + mi;
                const uint4* fp = (const uint4*)g_Wabf + ((long)(mb * 4 + ks) * 32 + lane) * 2;
                Ah[mi] = fp[0];
            }
            int bk = ks * 16 + (lane & 3) * 2;
#pragma unroll
            for (int ni = 0; ni < 8; ni++) {
                int bp = warpP + ni * 8 + (lane >> 2);
                unsigned bh0 = *(const unsigned*)&Bh[bp][bk];
                unsigned bh1 = *(const unsigned*)&Bh[bp][bk + 8];
#pragma unroll
                for (int mi = 0; mi < 2; mi++)
                    mma16816(acc[mi][ni], Ah[mi], bh0, bh1);
            }
        }
#pragma unroll
        for (int mi = 0; mi < 2; mi++) {
            int m = mtile * 128 + warpM + mi * 16 + (lane >> 2);
            float b0 = g_bab_pad[m], b1 = g_bab_pad[m + 8];
            __nv_bfloat16* op = g_abh + ((long)n * 256 + m) * TV + pBase + warpP + (lane & 3) * 2;
#pragma unroll
            for (int ni = 0; ni < 8; ni++) {
                __nv_bfloat162 p0, p1;
                p0.x = __float2bfloat16(acc[mi][ni][0] + b0);
                p0.y = __float2bfloat16(acc[mi][ni][1] + b0);
                p1.x = __float2bfloat16(acc[mi][ni][2] + b1);
                p1.y = __float2bfloat16(acc[mi][ni][3] + b1);
                if (m < 192)     *(__nv_bfloat162*)(op + ni * 8) = p0;
                if (m + 8 < 192) *(__nv_bfloat162*)(op + ni * 8 + 8L * TV) = p1;
            }
        }
    } else {
        // ---------- down path: 3-term, fp32 out, + stats partials ----------
#pragma unroll
        for (int ks = 0; ks < 4; ks++) {
            uint4 Ah[2], Al[2];
#pragma unroll
            for (int mi = 0; mi < 2; mi++) {
                int mb = (wid >> 1) * 2 + mi;
                const uint4* fp = (const uint4*)g_Wdnf + ((long)(mb * 4 + ks) * 32 + lane) * 2;
                Ah[mi] = fp[0];
                Al[mi] = fp[1];
            }
            int bk = ks * 16 + (lane & 3) * 2;
#pragma unroll
            for (int ni = 0; ni < 8; ni++) {
                int bp = warpP + ni * 8 + (lane >> 2);
                unsigned bh0 = *(const unsigned*)&Bh[bp][bk];
                unsigned bh1 = *(const unsigned*)&Bh[bp][bk + 8];
                unsigned bl0 = *(const unsigned*)&Bl[bp][bk];
                unsigned bl1 = *(const unsigned*)&Bl[bp][bk + 8];
#pragma unroll
                for (int mi = 0; mi < 2; mi++) {
                    mma16816(acc[mi][ni], Ah[mi], bh0, bh1);
                    mma16816(acc[mi][ni], Ah[mi], bl0, bl1);
                    mma16816(acc[mi][ni], Al[mi], bh0, bh1);
                }
            }
        }
        float ssum[2][2] = {}, ssq[2][2] = {};
#pragma unroll
        for (int mi = 0; mi < 2; mi++) {
            int m = warpM + mi * 16 + (lane >> 2);
            float b0 = bdown[m], b1 = bdown[m + 8];
            float* op = g_zd + ((long)n * 128 + m) * TV + pBase + warpP + (lane & 3) * 2;
#pragma unroll
            for (int ni = 0; ni < 8; ni++) {
                float v0 = acc[mi][ni][0] + b0, v1 = acc[mi][ni][1] + b0;
                float v2 = acc[mi][ni][2] + b1, v3 = acc[mi][ni][3] + b1;
                *(float2*)(op + ni * 8) = make_float2(v0, v1);
                *(float2*)(op + ni * 8 + 8L * TV) = make_float2(v2, v3);
                ssum[mi][0] += v0 + v1; ssq[mi][0] += v0 * v0 + v1 * v1;
                ssum[mi][1] += v2 + v3; ssq[mi][1] += v2 * v2 + v3 * v3;
            }
        }
#pragma unroll
        for (int mi = 0; mi < 2; mi++)
#pragma unroll
            for (int hi = 0; hi < 2; hi++) {
                float s = ssum[mi][hi], q = ssq[mi][hi];
                s += __shfl_xor_sync(0xffffffffu, s, 1);
                s += __shfl_xor_sync(0xffffffffu, s, 2);
                q += __shfl_xor_sync(0xffffffffu, q, 1);
                q += __shfl_xor_sync(0xffffffffu, q, 2);
                if ((lane & 3) == 0) {
                    redS[wid][lane >> 2][mi * 2 + hi] = s;
                    redQ[wid][lane >> 2][mi * 2 + hi] = q;
                }
            }
        __syncthreads();
        if (tid < 128) {
            int r = tid, mt = r >> 5, rr = r & 31;
            int mi = rr >> 4, hi = (rr >> 3) & 1, q8 = rr & 7;
            int w0 = mt * 2;
            float S = redS[w0][q8][mi * 2 + hi] + redS[w0 + 1][q8][mi * 2 + hi];
            float Q = redQ[w0][q8][mi * 2 + hi] + redQ[w0 + 1][q8][mi * 2 + hi];
            long idx = (((long)64 + n) * 50 + blockIdx.x) * 128 + r;
            g_psum[idx] = S;
            g_psq[idx] = Q;
        }
    }
}

// =============== GEMM: y = Wd_cat @ xs, bf16 in/out, + stats ===============
// grid (50, 1, 64)
__global__ __launch_bounds__(256, 2) void gemm_y_k() {
    __shared__ __align__(16) unsigned short Bh[128][LDB];
    __shared__ float redS[8][8][4], redQ[8][8][4];
    int tid = threadIdx.x, wid = tid >> 5, lane = tid & 31;
    int n = blockIdx.z, pBase = blockIdx.x * 128;
    int warpM = (wid >> 1) * 32, warpP = (wid & 1) * 64;
    float acc[2][8][4] = {};

    const __nv_bfloat16* inb = g_xsb + (long)n * (192L * TV) + pBase;
    int pq = tid & 63, skq = (tid >> 6) * 16;

    for (int kc = 0; kc < 3; kc++) {
        __syncthreads();
        const __nv_bfloat16* colb = inb + (long)(kc * 64 + skq) * TV + pq * 2;
#pragma unroll
        for (int j = 0; j < 16; j++) {
            __nv_bfloat162 v = *(const __nv_bfloat162*)(colb + (long)j * TV);
            Bh[pq * 2][skq + j]     = __bfloat16_as_ushort(v.x);
            Bh[pq * 2 + 1][skq + j] = __bfloat16_as_ushort(v.y);
        }
        __syncthreads();
#pragma unroll
        for (int ks = 0; ks < 4; ks++) {
            int kg = kc * 4 + ks;
            uint4 Ah[2];
#pragma unroll
            for (int mi = 0; mi < 2; mi++) {
                int mb = (wid >> 1) * 2 + mi;
                const uint4* fp = (const uint4*)g_Wyf + ((long)(mb * 12 + kg) * 32 + lane) * 2;
                Ah[mi] = fp[0];
            }
            int bk = ks * 16 + (lane & 3) * 2;
#pragma unroll
            for (int ni = 0; ni < 8; ni++) {
                int bp = warpP + ni * 8 + (lane >> 2);
                unsigned bh0 = *(const unsigned*)&Bh[bp][bk];
                unsigned bh1 = *(const unsigned*)&Bh[bp][bk + 8];
#pragma unroll
                for (int mi = 0; mi < 2; mi++)
                    mma16816(acc[mi][ni], Ah[mi], bh0, bh1);
            }
        }
    }

    float ssum[2][2] = {}, ssq[2][2] = {};
#pragma unroll
    for (int mi = 0; mi < 2; mi++) {
        int m = warpM + mi * 16 + (lane >> 2);
        float b0 = g_by[m], b1 = g_by[m + 8];
        __nv_bfloat16* op = g_zy + ((long)n * 128 + m) * TV + pBase + warpP + (lane & 3) * 2;
#pragma unroll
        for (int ni = 0; ni < 8; ni++) {
            float v0 = acc[mi][ni][0] + b0, v1 = acc[mi][ni][1] + b0;
            float v2 = acc[mi][ni][2] + b1, v3 = acc[mi][ni][3] + b1;
            __nv_bfloat162 p0, p1;
            p0.x = __float2bfloat16(v0); p0.y = __float2bfloat16(v1);
            p1.x = __float2bfloat16(v2); p1.y = __float2bfloat16(v3);
            *(__nv_bfloat162*)(op + ni * 8) = p0;
            *(__nv_bfloat162*)(op + ni * 8 + 8L * TV) = p1;
            ssum[mi][0] += v0 + v1; ssq[mi][0] += v0 * v0 + v1 * v1;
            ssum[mi][1] += v2 + v3; ssq[mi][1] += v2 * v2 + v3 * v3;
        }
    }
#pragma unroll
    for (int mi = 0; mi < 2; mi++)
#pragma unroll
        for (int hi = 0; hi < 2; hi++) {
            float s = ssum[mi][hi], q = ssq[mi][hi];
            s += __shfl_xor_sync(0xffffffffu, s, 1);
            s += __shfl_xor_sync(0xffffffffu, s, 2);
            q += __shfl_xor_sync(0xffffffffu, q, 1);
            q += __shfl_xor_sync(0xffffffffu, q, 2);
            if ((lane & 3) == 0) {
                redS[wid][lane >> 2][mi * 2 + hi] = s;
                redQ[wid][lane >> 2][mi * 2 + hi] = q;
            }
        }
    __syncthreads();
    if (tid < 128) {
        int r = tid, mt = r >> 5, rr = r & 31;
        int mi = rr >> 4, hi = (rr >> 3) & 1, q8 = rr & 7;
        int w0 = mt * 2;
        float S = redS[w0][q8][mi * 2 + hi] + redS[w0 + 1][q8][mi * 2 + hi];
        float Q = redQ[w0][q8][mi * 2 + hi] + redQ[w0 + 1][q8][mi * 2 + hi];
        long idx = ((long)n * 50 + blockIdx.x) * 128 + r;
        g_psum[idx] = S;
        g_psq[idx] = Q;
    }
}

// ============ logits via mma: lg[n,i,v,w] = sum_k a[k,v] b[k,w] ============
// grid (3, 64, 4). Warp (mt,nt) owns a 16x8 C tile; no cross-warp reduce.
__global__ __launch_bounds__(256) void logits_mma_kernel() {
    __shared__ unsigned short At[32][72];   // [v][k64], pitch 72 (conflict-free)
    __shared__ unsigned short Bt[32][72];   // [w][k64]
    int i = blockIdx.x, n = blockIdx.y, ks = blockIdx.z;
    int tid = threadIdx.x, wid = tid >> 5, lane = tid & 31;
    int mt = wid >> 2, nt = wid & 3;
    int lr = lane >> 2, kb = (lane & 3) * 2;

    for (int f = tid; f < 32 * 36; f += 256) {   // zero both (as uints)
        ((unsigned*)At)[f] = 0;
        ((unsigned*)Bt)[f] = 0;
    }
    float acc[4] = {0.f, 0.f, 0.f, 0.f};
    const __nv_bfloat16* abase = g_abh + ((long)n * 256 + i * 32) * TV;
    const __nv_bfloat16* bbase = abase + 96L * TV;

    for (int c = ks * 32; c < ks * 32 + 32; c++) {
        int r = c >> 2, t0 = (c & 3) * 64;
        const __nv_bfloat16* ap = abase + (long)r * TV + t0 * 25;
        const __nv_bfloat16* bp = bbase + (long)r * TV + t0 * 25;
        __syncthreads();
        for (int f = tid; f < 1600; f += 256) {
            int t = f / 25, v = f - t * 25;
            At[v][t] = __bfloat16_as_ushort(ap[f]);
            Bt[v][t] = __bfloat16_as_ushort(bp[f]);
        }
        __syncthreads();
#pragma unroll
        for (int kk = 0; kk < 4; kk++) {
            uint4 Af;
            int mrow = mt * 16 + lr;
            Af.x = *(const unsigned*)&At[mrow][kk * 16 + kb];
            Af.y = *(const unsigned*)&At[mrow + 8][kk * 16 + kb];
            Af.z = *(const unsigned*)&At[mrow][kk * 16 + kb + 8];
            Af.w = *(const unsigned*)&At[mrow + 8][kk * 16 + kb + 8];
            unsigned b0 = *(const unsigned*)&Bt[nt * 8 + lr][kk * 16 + kb];
            unsigned b1 = *(const unsigned*)&Bt[nt * 8 + lr][kk * 16 + kb + 8];
            mma16816(acc, Af, b0, b1);
        }
    }
    float* outp = g_part + ((long)ks * 192 + n * 3 + i) * 625;
    int v0 = mt * 16 + lr, w = nt * 8 + kb;
    if (w < 25) {
        bool w1 = (w + 1) < 25;
        if (v0 < 25)     { outp[v0 * 25 + w] = acc[0];       if (w1) outp[v0 * 25 + w + 1] = acc[1]; }
        if (v0 + 8 < 25) { outp[(v0 + 8) * 25 + w] = acc[2]; if (w1) outp[(v0 + 8) * 25 + w + 1] = acc[3]; }
    }
}

// ---------------- softmax over v (axis=1) per (n,i,w), + A_tot ------------
__global__ __launch_bounds__(256) void softmax_kernel() {
    int gid = blockIdx.x * blockDim.x + threadIdx.x;
    if (gid >= 64 * 3 * 25) return;
    int w = gid % 25;
    int i = (gid / 25) % 3;
    int n = gid / 75;
    const float* pp = g_part + (n * 3 + i) * 625 + w;
    float lg[25];
    float mx = -1e30f;
#pragma unroll
    for (int v = 0; v < 25; v++) {
        float s = (pp[v * 25] + pp[120000 + v * 25] + pp[240000 + v * 25]
                   + pp[360000 + v * 25]) * (1.f / 8192.f);
        lg[v] = s;
        mx = fmaxf(mx, s);
    }
    float sum = 0.f;
#pragma unroll
    for (int v = 0; v < 25; v++) { lg[v] = expf(lg[v] - mx); sum += lg[v]; }
    float inv = 1.f / sum;
    float* sp = g_S + (n * 3 + i) * 625 + w;
    const float* at = g_Atot + i * 625 + w;
#pragma unroll
    for (int v = 0; v < 25; v++) sp[v * 25] = lg[v] * inv + at[v * 25];
}

// ============ xs via mma: OUT[m,w] = sum_v IN[m,v] S[v,w], per (n,i) =======
// M=16384 (contiguous rows, pitch 25), K=25->32, N=25->32. grid (64 mtiles, 64 n).
__global__ __launch_bounds__(256) void xs_mma_kernel(const float* __restrict__ x) {
    __shared__ unsigned short As[256][40];     // [m][v], pitch 40 (conflict-free)
    __shared__ unsigned short Ss[3][32][40];   // [i][w][v] (col-major B)
    int tid = threadIdx.x, wid = tid >> 5, lane = tid & 31;
    int n = blockIdx.y, mt = blockIdx.x;
    int lr = lane >> 2, kb = (lane & 3) * 2;

    for (int f = tid; f < 5120; f += 256) ((unsigned*)As)[f] = 0;
    for (int f = tid; f < 1920; f += 256) ((unsigned*)Ss)[f] = 0;
    __syncthreads();

    const float* spt = g_S + (long)n * 1875;
    for (int f = tid; f < 1875; f += 256) {
        int i = f / 625, r = f - i * 625, v = r / 25, w = r - v * 25;
        Ss[i][w][v] = __bfloat16_as_ushort(__float2bfloat16(spt[f]));
    }
    const float* xb = x + (long)n * 409600 + (long)mt * 6400;
    for (int f = tid; f < 6400; f += 256) {
        int m = f / 25, v = f - m * 25;
        As[m][v] = __bfloat16_as_ushort(__float2bfloat16(xb[f]));
    }
    __syncthreads();

    for (int i = 0; i < 3; i++) {
        float acc[2][4][4] = {};
#pragma unroll
        for (int ksx = 0; ksx < 2; ksx++) {
            uint4 Af[2];
#pragma unroll
            for (int mi = 0; mi < 2; mi++) {
                int mrow = wid * 32 + mi * 16 + lr;
                Af[mi].x = *(const unsigned*)&As[mrow][ksx * 16 + kb];
                Af[mi].y = *(const unsigned*)&As[mrow + 8][ksx * 16 + kb];
                Af[mi].z = *(const unsigned*)&As[mrow][ksx * 16 + kb + 8];
                Af[mi].w = *(const unsigned*)&As[mrow + 8][ksx * 16 + kb + 8];
            }
#pragma unroll
            for (int nt = 0; nt < 4; nt++) {
                unsigned b0 = *(const unsigned*)&Ss[i][nt * 8 + lr][ksx * 16 + kb];
                unsigned b1 = *(const unsigned*)&Ss[i][nt * 8 + lr][ksx * 16 + kb + 8];
                mma16816(acc[0][nt], Af[0], b0, b1);
                mma16816(acc[1][nt], Af[1], b0, b1);
            }
        }
        // direct scalar bf16 stores (row pitch 25 is odd -> no vector stores)
        __nv_bfloat16* ob = g_xsb + (long)(n * 192 + i * 64) * 6400 + (long)mt * 6400;
#pragma unroll
        for (int mi = 0; mi < 2; mi++) {
            int mrow = wid * 32 + mi * 16 + lr;
#pragma unroll
            for (int nt = 0; nt < 4; nt++) {
                int w = nt * 8 + kb;
                if (w < 25) {
                    ob[(long)mrow * 25 + w] = __float2bfloat16(acc[mi][nt][0]);
                    ob[(long)(mrow + 8) * 25 + w] = __float2bfloat16(acc[mi][nt][2]);
                    if (w + 1 < 25) {
                        ob[(long)mrow * 25 + w + 1] = __float2bfloat16(acc[mi][nt][1]);
                        ob[(long)(mrow + 8) * 25 + w + 1] = __float2bfloat16(acc[mi][nt][3]);
                    }
                }
            }
        }
    }
}

// ---------------- stats reduce: per-channel mean/var from block partials ---
__global__ __launch_bounds__(256) void stats_reduce(
    const float* __restrict__ gbn, const float* __restrict__ bbn,
    const float* __restrict__ gdn, const float* __restrict__ bdn)
{
    int qch = blockIdx.x;            // 0..255 ; <128 = y, >=128 = down
    int half = qch >> 7, r = qch & 127;
    int tid = threadIdx.x;
    float s = 0.f, q = 0.f;
    for (int f = tid; f < 3200; f += 256) {
        long idx = (((long)half * 64 + f / 50) * 50 + (f % 50)) * 128 + r;
        s += g_psum[idx];
        q += g_psq[idx];
    }
    __shared__ float rs[256], rq[256];
    rs[tid] = s; rq[tid] = q;
    __syncthreads();
    for (int st = 128; st > 0; st >>= 1) {
        if (tid < st) { rs[tid] += rs[tid + st]; rq[tid] += rq[tid + st]; }
        __syncthreads();
    }
    if (tid == 0) {
        const float inv_m = 1.f / 409600.f;
        float mean = rs[0] * inv_m;
        float var  = rq[0] * inv_m - mean * mean;
        float rinv = rsqrtf(var + 1e-5f);
        float gamma = half ? gdn[r] : gbn[r];
        float beta  = half ? bdn[r] : bbn[r];
        g_alpha[qch] = gamma * rinv;
        g_bet[qch]   = beta - mean * gamma * rinv;
    }
}

// ---------------- fused epilogue: out = BN_y(y) + BN_d(down) ---------------
__global__ __launch_bounds__(256) void final_kernel(float* __restrict__ out) {
    int idx = blockIdx.x * 256 + threadIdx.x;
    int p4 = idx % 1600;
    int o  = (idx / 1600) & 127;
    int n  = idx / 204800;
    long e = ((long)n * 128 + o) * TV + p4 * 4;
    uint2 yb = *(const uint2*)(g_zy + e);
    __nv_bfloat162 y01 = *(__nv_bfloat162*)&yb.x;
    __nv_bfloat162 y23 = *(__nv_bfloat162*)&yb.y;
    float4 zd = *(const float4*)(g_zd + e);
    float a1 = g_alpha[o],       c1 = g_bet[o];
    float a2 = g_alpha[o + 128], c2 = g_bet[o + 128];
    float4 r;
    r.x = fmaf(a1, __bfloat162float(y01.x), c1) + fmaf(a2, zd.x, c2);
    r.y = fmaf(a1, __bfloat162float(y01.y), c1) + fmaf(a2, zd.y, c2);
    r.z = fmaf(a1, __bfloat162float(y23.x), c1) + fmaf(a2, zd.z, c2);
    r.w = fmaf(a1, __bfloat162float(y23.y), c1) + fmaf(a2, zd.w, c2);
    ((float4*)out)[idx] = r;
}

// ---------------- launcher -------------------------------------------------
extern "C" void kernel_launch(void* const* d_in, const int* in_sizes, int n_in,
                              void* d_out, int out_size) {
    const float* x     = (const float*)d_in[0];
    const float* A     = (const float*)d_in[1];
    const float* PA    = (const float*)d_in[2];
    const float* Wa    = (const float*)d_in[3];
    const float* ba    = (const float*)d_in[4];
    const float* Wb    = (const float*)d_in[5];
    const float* bb    = (const float*)d_in[6];
    const float* Wd    = (const float*)d_in[7];
    const float* bd    = (const float*)d_in[8];
    const float* Wdown = (const float*)d_in[9];
    const float* bdown = (const float*)d_in[10];
    const float* gbn   = (const float*)d_in[11];
    const float* bbn   = (const float*)d_in[12];
    const float* gdn   = (const float*)d_in[13];
    const float* bdn   = (const float*)d_in[14];
    float* out = (float*)d_out;

    prep_kernel<<<48, 256>>>(Wa, ba, Wb, bb, Wd, bd, Wdown, A, PA);

    // a|b -> g_abh (bf16) [mtiles 0,1] + down -> g_zd (fp32)+stats [mtile 2]
    gemm_abdn_k<<<dim3(50, 3, 64), 256>>>(x, bdown);

    logits_mma_kernel<<<dim3(3, 64, 4), 256>>>();
    softmax_kernel<<<19, 256>>>();
    xs_mma_kernel<<<dim3(64, 64), 256>>>(x);      // xs -> g_xsb (bf16)

    gemm_y_k<<<dim3(50, 1, 64), 256>>>();         // y -> g_zy (bf16) + stats partials

    stats_reduce<<<256, 256>>>(gbn, bbn, gdn, bdn);
    final_kernel<<<51200, 256>>>(out);
}

// round 11
// speedup vs baseline: 3.9491x; 1.1952x over previous
#include <cuda_runtime.h>
#include <cuda_bf16.h>
#include <cstdint>

#define TV 6400           // T*V = 256*25
#define NBATCH 64

// ---------------- scratch (device globals; no allocation allowed) ----------
__device__ __nv_bfloat16 g_abh[104857600]; // (64,256,6400) bf16: a/b conv out (rows 0..191 used)
__device__ __nv_bfloat16 g_xsb[78643200];  // (64,192,6400) bf16: xs (S-mixed x)
__device__ __nv_bfloat16 g_zy[52428800];   // (64,128,6400) bf16: y pre-BN
__device__ float g_zd[52428800];           // (64,128,6400) fp32: down pre-BN
__device__ float g_part[480000];    // (4,64,3,625) split-K logits partials
__device__ float g_S[120000];       // (64,3,25,25) final mixing matrix
__device__ float g_Atot[1875];      // A + PA
__device__ float g_by[128];         // sum_i bd[i]
__device__ float g_bab_pad[256];    // [ba|bb|0pad]
__device__ float g_alpha[256];      // BN fused scale
__device__ float g_bet[256];        // BN fused shift
__device__ float g_psum[819200];    // (2,64,50,128) per-block channel sums
__device__ float g_psq[819200];     // (2,64,50,128) per-block channel sumsq
// weights pre-packed in m16n8k16 A-fragment order (hi uint4 then lo uint4 per lane)
__device__ __align__(16) unsigned g_Wabf[16384];  // 16 mb x 4 ks x 32 x 8
__device__ __align__(16) unsigned g_Wyf[24576];   // 8 mb x 12 ks x 32 x 8
__device__ __align__(16) unsigned g_Wdnf[8192];   // 8 mb x 4 ks x 32 x 8

// ---------------- bf16 hi/lo split helpers ---------------------------------
__device__ __forceinline__ unsigned short bf_hi(float v) {
    return __bfloat16_as_ushort(__float2bfloat16(v));
}
__device__ __forceinline__ unsigned short bf_lo(float v) {
    __nv_bfloat16 h = __float2bfloat16(v);
    return __bfloat16_as_ushort(__float2bfloat16(v - __bfloat162float(h)));
}
__device__ __forceinline__ unsigned pack_hi(float v0, float v1) {
    return (unsigned)bf_hi(v0) | ((unsigned)bf_hi(v1) << 16);
}
__device__ __forceinline__ unsigned pack_lo(float v0, float v1) {
    return (unsigned)bf_lo(v0) | ((unsigned)bf_lo(v1) << 16);
}

// ---------------- prep: biases, A+PA, fragment-packed weights --------------
__device__ __forceinline__ void frag_decode(int f, int nK16,
                                            int& row, int& col, bool& hi) {
    int r = f & 7, slot = f >> 3;
    int lane = slot & 31, t2 = slot >> 5;
    int ks = t2 % nK16, mb = t2 / nK16;
    int rr = r & 3;
    row = mb * 16 + (lane >> 2) + ((rr & 1) << 3);
    col = ks * 16 + (lane & 3) * 2 + ((rr & 2) << 2);
    hi = r < 4;
}

__global__ __launch_bounds__(256) void prep_kernel(
    const float* __restrict__ Wa, const float* __restrict__ ba,
    const float* __restrict__ Wb, const float* __restrict__ bb,
    const float* __restrict__ Wd, const float* __restrict__ bd,
    const float* __restrict__ Wdown,
    const float* __restrict__ A,  const float* __restrict__ PA)
{
    int stride = gridDim.x * blockDim.x;
    int g = blockIdx.x * blockDim.x + threadIdx.x;
    for (int f = g; f < 256; f += stride)
        g_bab_pad[f] = (f < 96) ? ba[f] : (f < 192 ? bb[f - 96] : 0.f);
    for (int f = g; f < 128; f += stride)
        g_by[f] = bd[f] + bd[128 + f] + bd[256 + f];
    for (int f = g; f < 1875; f += stride)
        g_Atot[f] = A[f] + PA[f];

    for (int f = g; f < 16384; f += stride) {
        int row, col; bool hi;
        frag_decode(f, 4, row, col, hi);
        float v0 = 0.f, v1 = 0.f;
        if (row < 96)       { v0 = Wa[row * 64 + col]; v1 = Wa[row * 64 + col + 1]; }
        else if (row < 192) { v0 = Wb[(row - 96) * 64 + col]; v1 = Wb[(row - 96) * 64 + col + 1]; }
        g_Wabf[f] = hi ? pack_hi(v0, v1) : pack_lo(v0, v1);
    }
    for (int f = g; f < 24576; f += stride) {
        int row, col; bool hi;
        frag_decode(f, 12, row, col, hi);
        int i = col >> 6, c = col & 63;
        float v0 = Wd[(i * 128 + row) * 64 + c];
        float v1 = Wd[(i * 128 + row) * 64 + c + 1];
        g_Wyf[f] = hi ? pack_hi(v0, v1) : pack_lo(v0, v1);
    }
    for (int f = g; f < 8192; f += stride) {
        int row, col; bool hi;
        frag_decode(f, 4, row, col, hi);
        float v0 = Wdown[row * 64 + col], v1 = Wdown[row * 64 + col + 1];
        g_Wdnf[f] = hi ? pack_hi(v0, v1) : pack_lo(v0, v1);
    }
}

// ---------------- mma.sync wrapper -----------------------------------------
__device__ __forceinline__ void mma16816(float* c, const uint4& a,
                                         unsigned b0, unsigned b1) {
    asm volatile(
        "mma.sync.aligned.m16n8k16.row.col.f32.bf16.bf16.f32 "
        "{%0,%1,%2,%3}, {%4,%5,%6,%7}, {%8,%9}, {%0,%1,%2,%3};"
        : "+f"(c[0]), "+f"(c[1]), "+f"(c[2]), "+f"(c[3])
        : "r"(a.x), "r"(a.y), "r"(a.z), "r"(a.w), "r"(b0), "r"(b1));
}

#define LDB 72   // smem row pitch (144B -> conflict-free fragment LDS)

// ========== fused GEMM: ab (mtile 0,1) + down (mtile 2); shares x read =====
// grid (50, 3, 64); block 256.
__global__ __launch_bounds__(256, 2) void gemm_abdn_k(const float* __restrict__ x,
                                                      const float* __restrict__ bdown) {
    __shared__ __align__(16) unsigned short Bh[128][LDB];
    __shared__ __align__(16) unsigned short Bl[128][LDB];
    __shared__ float redS[8][8][4], redQ[8][8][4];
    int tid = threadIdx.x, wid = tid >> 5, lane = tid & 31;
    int n = blockIdx.z, pBase = blockIdx.x * 128, mtile = blockIdx.y;
    int warpM = (wid >> 1) * 32, warpP = (wid & 1) * 64;
    float acc[2][8][4] = {};

    const float* inp = x + (long)n * (64L * TV) + pBase;
    int sp = tid & 127, skh = (tid >> 7) * 32;
    const float* colp = inp + (long)skh * TV + sp;
#pragma unroll
    for (int j = 0; j < 32; j += 2) {
        float v0 = colp[(long)j * TV];
        float v1 = colp[(long)(j + 1) * TV];
        *(unsigned*)&Bh[sp][skh + j] = pack_hi(v0, v1);
        if (mtile == 2)   // lo-half only needed by the 3-term down path
            *(unsigned*)&Bl[sp][skh + j] = pack_lo(v0, v1);
    }
    __syncthreads();

    if (mtile < 2) {
        // ---------- ab path: single-term bf16, staged bf16 out -------------
#pragma unroll
        for (int ks = 0; ks < 4; ks++) {
            uint4 Ah[2];
#pragma unroll
            for (int mi = 0; mi < 2; mi++) {
                int mb = mtile * 8 + (wid >> 1) * 2 + mi;
                const uint4* fp = (const uint4*)g_Wabf + ((long)(mb * 4 + ks) * 32 + lane) * 2;
                Ah[mi] = fp[0];
            }
            int bk = ks * 16 + (lane & 3) * 2;
#pragma unroll
            for (int ni = 0; ni < 8; ni++) {
                int bp = warpP + ni * 8 + (lane >> 2);
                unsigned bh0 = *(const unsigned*)&Bh[bp][bk];
                unsigned bh1 = *(const unsigned*)&Bh[bp][bk + 8];
#pragma unroll
                for (int mi = 0; mi < 2; mi++)
                    mma16816(acc[mi][ni], Ah[mi], bh0, bh1);
            }
        }
        // staged epilogue: two 64-row halves through Bh (pitch 136: no conflicts)
        __syncthreads();
        unsigned short (*St)[136] = (unsigned short(*)[136])Bh;
#pragma unroll
        for (int h = 0; h < 2; h++) {
            if ((wid >> 2) == h) {
#pragma unroll
                for (int mi = 0; mi < 2; mi++) {
                    int m = mtile * 128 + warpM + mi * 16 + (lane >> 2);
                    float b0 = g_bab_pad[m], b1 = g_bab_pad[m + 8];
                    int r0 = warpM - h * 64 + mi * 16 + (lane >> 2);
#pragma unroll
                    for (int ni = 0; ni < 8; ni++) {
                        int col = warpP + ni * 8 + (lane & 3) * 2;
                        __nv_bfloat162 p0, p1;
                        p0.x = __float2bfloat16(acc[mi][ni][0] + b0);
                        p0.y = __float2bfloat16(acc[mi][ni][1] + b0);
                        p1.x = __float2bfloat16(acc[mi][ni][2] + b1);
                        p1.y = __float2bfloat16(acc[mi][ni][3] + b1);
                        *(__nv_bfloat162*)&St[r0][col] = p0;
                        *(__nv_bfloat162*)&St[r0 + 8][col] = p1;
                    }
                }
            }
            __syncthreads();
            int m0 = mtile * 128 + h * 64;
            for (int f = tid; f < 1024; f += 256) {
                int r = f >> 4, c = f & 15;
                int m = m0 + r;
                if (m < 192) {
                    uint4 v = *(const uint4*)&St[r][c * 8];
                    *(uint4*)(g_abh + ((long)n * 256 + m) * TV + pBase + c * 8) = v;
                }
            }
            __syncthreads();
        }
    } else {
        // ---------- down path: 3-term, fp32 out (full-sector), + stats -----
#pragma unroll
        for (int ks = 0; ks < 4; ks++) {
            uint4 Ah[2], Al[2];
#pragma unroll
            for (int mi = 0; mi < 2; mi++) {
                int mb = (wid >> 1) * 2 + mi;
                const uint4* fp = (const uint4*)g_Wdnf + ((long)(mb * 4 + ks) * 32 + lane) * 2;
                Ah[mi] = fp[0];
                Al[mi] = fp[1];
            }
            int bk = ks * 16 + (lane & 3) * 2;
#pragma unroll
            for (int ni = 0; ni < 8; ni++) {
                int bp = warpP + ni * 8 + (lane >> 2);
                unsigned bh0 = *(const unsigned*)&Bh[bp][bk];
                unsigned bh1 = *(const unsigned*)&Bh[bp][bk + 8];
                unsigned bl0 = *(const unsigned*)&Bl[bp][bk];
                unsigned bl1 = *(const unsigned*)&Bl[bp][bk + 8];
#pragma unroll
                for (int mi = 0; mi < 2; mi++) {
                    mma16816(acc[mi][ni], Ah[mi], bh0, bh1);
                    mma16816(acc[mi][ni], Ah[mi], bl0, bl1);
                    mma16816(acc[mi][ni], Al[mi], bh0, bh1);
                }
            }
        }
        float ssum[2][2] = {}, ssq[2][2] = {};
#pragma unroll
        for (int mi = 0; mi < 2; mi++) {
            int m = warpM + mi * 16 + (lane >> 2);
            float b0 = bdown[m], b1 = bdown[m + 8];
            float* op = g_zd + ((long)n * 128 + m) * TV + pBase + warpP + (lane & 3) * 2;
#pragma unroll
            for (int ni = 0; ni < 8; ni++) {
                float v0 = acc[mi][ni][0] + b0, v1 = acc[mi][ni][1] + b0;
                float v2 = acc[mi][ni][2] + b1, v3 = acc[mi][ni][3] + b1;
                *(float2*)(op + ni * 8) = make_float2(v0, v1);
                *(float2*)(op + ni * 8 + 8L * TV) = make_float2(v2, v3);
                ssum[mi][0] += v0 + v1; ssq[mi][0] += v0 * v0 + v1 * v1;
                ssum[mi][1] += v2 + v3; ssq[mi][1] += v2 * v2 + v3 * v3;
            }
        }
#pragma unroll
        for (int mi = 0; mi < 2; mi++)
#pragma unroll
            for (int hi = 0; hi < 2; hi++) {
                float s = ssum[mi][hi], q = ssq[mi][hi];
                s += __shfl_xor_sync(0xffffffffu, s, 1);
                s += __shfl_xor_sync(0xffffffffu, s, 2);
                q += __shfl_xor_sync(0xffffffffu, q, 1);
                q += __shfl_xor_sync(0xffffffffu, q, 2);
                if ((lane & 3) == 0) {
                    redS[wid][lane >> 2][mi * 2 + hi] = s;
                    redQ[wid][lane >> 2][mi * 2 + hi] = q;
                }
            }
        __syncthreads();
        if (tid < 128) {
            int r = tid, mt = r >> 5, rr = r & 31;
            int mi = rr >> 4, hi = (rr >> 3) & 1, q8 = rr & 7;
            int w0 = mt * 2;
            float S = redS[w0][q8][mi * 2 + hi] + redS[w0 + 1][q8][mi * 2 + hi];
            float Q = redQ[w0][q8][mi * 2 + hi] + redQ[w0 + 1][q8][mi * 2 + hi];
            long idx = (((long)64 + n) * 50 + blockIdx.x) * 128 + r;
            g_psum[idx] = S;
            g_psq[idx] = Q;
        }
    }
}

// =============== GEMM: y = Wd_cat @ xs, bf16 in/out, + stats ===============
// grid (50, 1, 64)
__global__ __launch_bounds__(256, 2) void gemm_y_k() {
    __shared__ __align__(16) unsigned short Bh[128][LDB];
    __shared__ float redS[8][8][4], redQ[8][8][4];
    int tid = threadIdx.x, wid = tid >> 5, lane = tid & 31;
    int n = blockIdx.z, pBase = blockIdx.x * 128;
    int warpM = (wid >> 1) * 32, warpP = (wid & 1) * 64;
    float acc[2][8][4] = {};

    const __nv_bfloat16* inb = g_xsb + (long)n * (192L * TV) + pBase;
    int pq = tid & 63, skq = (tid >> 6) * 16;

    for (int kc = 0; kc < 3; kc++) {
        __syncthreads();
        const __nv_bfloat16* colb = inb + (long)(kc * 64 + skq) * TV + pq * 2;
#pragma unroll
        for (int j = 0; j < 16; j++) {
            __nv_bfloat162 v = *(const __nv_bfloat162*)(colb + (long)j * TV);
            Bh[pq * 2][skq + j]     = __bfloat16_as_ushort(v.x);
            Bh[pq * 2 + 1][skq + j] = __bfloat16_as_ushort(v.y);
        }
        __syncthreads();
#pragma unroll
        for (int ks = 0; ks < 4; ks++) {
            int kg = kc * 4 + ks;
            uint4 Ah[2];
#pragma unroll
            for (int mi = 0; mi < 2; mi++) {
                int mb = (wid >> 1) * 2 + mi;
                const uint4* fp = (const uint4*)g_Wyf + ((long)(mb * 12 + kg) * 32 + lane) * 2;
                Ah[mi] = fp[0];
            }
            int bk = ks * 16 + (lane & 3) * 2;
#pragma unroll
            for (int ni = 0; ni < 8; ni++) {
                int bp = warpP + ni * 8 + (lane >> 2);
                unsigned bh0 = *(const unsigned*)&Bh[bp][bk];
                unsigned bh1 = *(const unsigned*)&Bh[bp][bk + 8];
#pragma unroll
                for (int mi = 0; mi < 2; mi++)
                    mma16816(acc[mi][ni], Ah[mi], bh0, bh1);
            }
        }
    }

    // ---- stats from fp32 accumulators ----
    float ssum[2][2] = {}, ssq[2][2] = {};
#pragma unroll
    for (int mi = 0; mi < 2; mi++) {
        int m = warpM + mi * 16 + (lane >> 2);
        float b0 = g_by[m], b1 = g_by[m + 8];
#pragma unroll
        for (int ni = 0; ni < 8; ni++) {
            float v0 = acc[mi][ni][0] + b0, v1 = acc[mi][ni][1] + b0;
            float v2 = acc[mi][ni][2] + b1, v3 = acc[mi][ni][3] + b1;
            ssum[mi][0] += v0 + v1; ssq[mi][0] += v0 * v0 + v1 * v1;
            ssum[mi][1] += v2 + v3; ssq[mi][1] += v2 * v2 + v3 * v3;
        }
    }
#pragma unroll
    for (int mi = 0; mi < 2; mi++)
#pragma unroll
        for (int hi = 0; hi < 2; hi++) {
            float s = ssum[mi][hi], q = ssq[mi][hi];
            s += __shfl_xor_sync(0xffffffffu, s, 1);
            s += __shfl_xor_sync(0xffffffffu, s, 2);
            q += __shfl_xor_sync(0xffffffffu, q, 1);
            q += __shfl_xor_sync(0xffffffffu, q, 2);
            if ((lane & 3) == 0) {
                redS[wid][lane >> 2][mi * 2 + hi] = s;
                redQ[wid][lane >> 2][mi * 2 + hi] = q;
            }
        }
    __syncthreads();
    if (tid < 128) {
        int r = tid, mt = r >> 5, rr = r & 31;
        int mi = rr >> 4, hi = (rr >> 3) & 1, q8 = rr & 7;
        int w0 = mt * 2;
        float S = redS[w0][q8][mi * 2 + hi] + redS[w0 + 1][q8][mi * 2 + hi];
        float Q = redQ[w0][q8][mi * 2 + hi] + redQ[w0 + 1][q8][mi * 2 + hi];
        long idx = ((long)n * 50 + blockIdx.x) * 128 + r;
        g_psum[idx] = S;
        g_psq[idx] = Q;
    }

    // ---- staged epilogue through Bh ----
    __syncthreads();
    unsigned short (*St)[136] = (unsigned short(*)[136])Bh;
#pragma unroll
    for (int h = 0; h < 2; h++) {
        if ((wid >> 2) == h) {
#pragma unroll
            for (int mi = 0; mi < 2; mi++) {
                int m = warpM + mi * 16 + (lane >> 2);
                float b0 = g_by[m], b1 = g_by[m + 8];
                int r0 = warpM - h * 64 + mi * 16 + (lane >> 2);
#pragma unroll
                for (int ni = 0; ni < 8; ni++) {
                    int col = warpP + ni * 8 + (lane & 3) * 2;
                    __nv_bfloat162 p0, p1;
                    p0.x = __float2bfloat16(acc[mi][ni][0] + b0);
                    p0.y = __float2bfloat16(acc[mi][ni][1] + b0);
                    p1.x = __float2bfloat16(acc[mi][ni][2] + b1);
                    p1.y = __float2bfloat16(acc[mi][ni][3] + b1);
                    *(__nv_bfloat162*)&St[r0][col] = p0;
                    *(__nv_bfloat162*)&St[r0 + 8][col] = p1;
                }
            }
        }
        __syncthreads();
        int m0 = h * 64;
        for (int f = tid; f < 1024; f += 256) {
            int r = f >> 4, c = f & 15;
            uint4 v = *(const uint4*)&St[r][c * 8];
            *(uint4*)(g_zy + ((long)n * 128 + m0 + r) * TV + pBase + c * 8) = v;
        }
        __syncthreads();
    }
}

// ============ logits via mma: lg[n,i,v,w] = sum_k a[k,v] b[k,w] ============
// grid (3, 64, 4). Warp (mt,nt) owns a 16x8 C tile; no cross-warp reduce.
__global__ __launch_bounds__(256) void logits_mma_kernel() {
    __shared__ unsigned short At[32][72];   // [v][k64], pitch 72 (conflict-free)
    __shared__ unsigned short Bt[32][72];   // [w][k64]
    int i = blockIdx.x, n = blockIdx.y, ks = blockIdx.z;
    int tid = threadIdx.x, wid = tid >> 5, lane = tid & 31;
    int mt = wid >> 2, nt = wid & 3;
    int lr = lane >> 2, kb = (lane & 3) * 2;

    for (int f = tid; f < 32 * 36; f += 256) {   // zero both (as uints)
        ((unsigned*)At)[f] = 0;
        ((unsigned*)Bt)[f] = 0;
    }
    float acc[4] = {0.f, 0.f, 0.f, 0.f};
    const __nv_bfloat16* abase = g_abh + ((long)n * 256 + i * 32) * TV;
    const __nv_bfloat16* bbase = abase + 96L * TV;

    for (int c = ks * 32; c < ks * 32 + 32; c++) {
        int r = c >> 2, t0 = (c & 3) * 64;
        const __nv_bfloat16* ap = abase + (long)r * TV + t0 * 25;
        const __nv_bfloat16* bp = bbase + (long)r * TV + t0 * 25;
        __syncthreads();
        for (int f = tid; f < 1600; f += 256) {
            int t = f / 25, v = f - t * 25;
            At[v][t] = __bfloat16_as_ushort(ap[f]);
            Bt[v][t] = __bfloat16_as_ushort(bp[f]);
        }
        __syncthreads();
#pragma unroll
        for (int kk = 0; kk < 4; kk++) {
            uint4 Af;
            int mrow = mt * 16 + lr;
            Af.x = *(const unsigned*)&At[mrow][kk * 16 + kb];
            Af.y = *(const unsigned*)&At[mrow + 8][kk * 16 + kb];
            Af.z = *(const unsigned*)&At[mrow][kk * 16 + kb + 8];
            Af.w = *(const unsigned*)&At[mrow + 8][kk * 16 + kb + 8];
            unsigned b0 = *(const unsigned*)&Bt[nt * 8 + lr][kk * 16 + kb];
            unsigned b1 = *(const unsigned*)&Bt[nt * 8 + lr][kk * 16 + kb + 8];
            mma16816(acc, Af, b0, b1);
        }
    }
    float* outp = g_part + ((long)ks * 192 + n * 3 + i) * 625;
    int v0 = mt * 16 + lr, w = nt * 8 + kb;
    if (w < 25) {
        bool w1 = (w + 1) < 25;
        if (v0 < 25)     { outp[v0 * 25 + w] = acc[0];       if (w1) outp[v0 * 25 + w + 1] = acc[1]; }
        if (v0 + 8 < 25) { outp[(v0 + 8) * 25 + w] = acc[2]; if (w1) outp[(v0 + 8) * 25 + w + 1] = acc[3]; }
    }
}

// ---------------- softmax over v (axis=1) per (n,i,w), + A_tot ------------
__global__ __launch_bounds__(256) void softmax_kernel() {
    int gid = blockIdx.x * blockDim.x + threadIdx.x;
    if (gid >= 64 * 3 * 25) return;
    int w = gid % 25;
    int i = (gid / 25) % 3;
    int n = gid / 75;
    const float* pp = g_part + (n * 3 + i) * 625 + w;
    float lg[25];
    float mx = -1e30f;
#pragma unroll
    for (int v = 0; v < 25; v++) {
        float s = (pp[v * 25] + pp[120000 + v * 25] + pp[240000 + v * 25]
                   + pp[360000 + v * 25]) * (1.f / 8192.f);
        lg[v] = s;
        mx = fmaxf(mx, s);
    }
    float sum = 0.f;
#pragma unroll
    for (int v = 0; v < 25; v++) { lg[v] = expf(lg[v] - mx); sum += lg[v]; }
    float inv = 1.f / sum;
    float* sp = g_S + (n * 3 + i) * 625 + w;
    const float* at = g_Atot + i * 625 + w;
#pragma unroll
    for (int v = 0; v < 25; v++) sp[v * 25] = lg[v] * inv + at[v * 25];
}

// ============ xs via mma: OUT[m,w] = sum_v IN[m,v] S[v,w], per (n,i) =======
// M=16384 (contiguous rows, pitch 25), K=25->32, N=25->32. grid (64 mtiles, 64 n).
// Output staged in smem -> fully coalesced uint4 stores (kills sector waste).
__global__ __launch_bounds__(256) void xs_mma_kernel(const float* __restrict__ x) {
    __shared__ unsigned short As[256][40];     // [m][v], pitch 40 (conflict-free)
    __shared__ unsigned short Ss[3][32][40];   // [i][w][v] (col-major B)
    __shared__ __align__(16) unsigned short Os[6400];  // staged output tile
    int tid = threadIdx.x, wid = tid >> 5, lane = tid & 31;
    int n = blockIdx.y, mt = blockIdx.x;
    int lr = lane >> 2, kb = (lane & 3) * 2;

    for (int f = tid; f < 5120; f += 256) ((unsigned*)As)[f] = 0;
    for (int f = tid; f < 1920; f += 256) ((unsigned*)Ss)[f] = 0;
    __syncthreads();

    const float* spt = g_S + (long)n * 1875;
    for (int f = tid; f < 1875; f += 256) {
        int i = f / 625, r = f - i * 625, v = r / 25, w = r - v * 25;
        Ss[i][w][v] = __bfloat16_as_ushort(__float2bfloat16(spt[f]));
    }
    const float* xb = x + (long)n * 409600 + (long)mt * 6400;
    for (int f = tid; f < 6400; f += 256) {
        int m = f / 25, v = f - m * 25;
        As[m][v] = __bfloat16_as_ushort(__float2bfloat16(xb[f]));
    }
    __syncthreads();

    for (int i = 0; i < 3; i++) {
        float acc[2][4][4] = {};
#pragma unroll
        for (int ksx = 0; ksx < 2; ksx++) {
            uint4 Af[2];
#pragma unroll
            for (int mi = 0; mi < 2; mi++) {
                int mrow = wid * 32 + mi * 16 + lr;
                Af[mi].x = *(const unsigned*)&As[mrow][ksx * 16 + kb];
                Af[mi].y = *(const unsigned*)&As[mrow + 8][ksx * 16 + kb];
                Af[mi].z = *(const unsigned*)&As[mrow][ksx * 16 + kb + 8];
                Af[mi].w = *(const unsigned*)&As[mrow + 8][ksx * 16 + kb + 8];
            }
#pragma unroll
            for (int nt = 0; nt < 4; nt++) {
                unsigned b0 = *(const unsigned*)&Ss[i][nt * 8 + lr][ksx * 16 + kb];
                unsigned b1 = *(const unsigned*)&Ss[i][nt * 8 + lr][ksx * 16 + kb + 8];
                mma16816(acc[0][nt], Af[0], b0, b1);
                mma16816(acc[1][nt], Af[1], b0, b1);
            }
        }
        // stage into Os (scalar bf16 STS; pitch 25)
#pragma unroll
        for (int mi = 0; mi < 2; mi++) {
            int mrow = wid * 32 + mi * 16 + lr;
#pragma unroll
            for (int nt = 0; nt < 4; nt++) {
                int w = nt * 8 + kb;
                if (w < 25) {
                    Os[mrow * 25 + w] = __bfloat16_as_ushort(__float2bfloat16(acc[mi][nt][0]));
                    Os[(mrow + 8) * 25 + w] = __bfloat16_as_ushort(__float2bfloat16(acc[mi][nt][2]));
                    if (w + 1 < 25) {
                        Os[mrow * 25 + w + 1] = __bfloat16_as_ushort(__float2bfloat16(acc[mi][nt][1]));
                        Os[(mrow + 8) * 25 + w + 1] = __bfloat16_as_ushort(__float2bfloat16(acc[mi][nt][3]));
                    }
                }
            }
        }
        __syncthreads();
        // coalesced uint4 stores: 6400 bf16 = 800 uint4, fully contiguous
        const uint4* os4 = (const uint4*)Os;
        uint4* ob4 = (uint4*)(g_xsb + (long)(n * 192 + i * 64 + mt) * 6400);
        for (int f = tid; f < 800; f += 256) ob4[f] = os4[f];
        __syncthreads();
    }
}

// ---------------- stats reduce: per-channel mean/var from block partials ---
__global__ __launch_bounds__(256) void stats_reduce(
    const float* __restrict__ gbn, const float* __restrict__ bbn,
    const float* __restrict__ gdn, const float* __restrict__ bdn)
{
    int qch = blockIdx.x;            // 0..255 ; <128 = y, >=128 = down
    int half = qch >> 7, r = qch & 127;
    int tid = threadIdx.x;
    float s = 0.f, q = 0.f;
    for (int f = tid; f < 3200; f += 256) {
        long idx = (((long)half * 64 + f / 50) * 50 + (f % 50)) * 128 + r;
        s += g_psum[idx];
        q += g_psq[idx];
    }
    __shared__ float rs[256], rq[256];
    rs[tid] = s; rq[tid] = q;
    __syncthreads();
    for (int st = 128; st > 0; st >>= 1) {
        if (tid < st) { rs[tid] += rs[tid + st]; rq[tid] += rq[tid + st]; }
        __syncthreads();
    }
    if (tid == 0) {
        const float inv_m = 1.f / 409600.f;
        float mean = rs[0] * inv_m;
        float var  = rq[0] * inv_m - mean * mean;
        float rinv = rsqrtf(var + 1e-5f);
        float gamma = half ? gdn[r] : gbn[r];
        float beta  = half ? bdn[r] : bbn[r];
        g_alpha[qch] = gamma * rinv;
        g_bet[qch]   = beta - mean * gamma * rinv;
    }
}

// ---------------- fused epilogue: out = BN_y(y) + BN_d(down) ---------------
__global__ __launch_bounds__(256) void final_kernel(float* __restrict__ out) {
    int idx = blockIdx.x * 256 + threadIdx.x;
    int p4 = idx % 1600;
    int o  = (idx / 1600) & 127;
    int n  = idx / 204800;
    long e = ((long)n * 128 + o) * TV + p4 * 4;
    uint2 yb = *(const uint2*)(g_zy + e);
    __nv_bfloat162 y01 = *(__nv_bfloat162*)&yb.x;
    __nv_bfloat162 y23 = *(__nv_bfloat162*)&yb.y;
    float4 zd = *(const float4*)(g_zd + e);
    float a1 = g_alpha[o],       c1 = g_bet[o];
    float a2 = g_alpha[o + 128], c2 = g_bet[o + 128];
    float4 r;
    r.x = fmaf(a1, __bfloat162float(y01.x), c1) + fmaf(a2, zd.x, c2);
    r.y = fmaf(a1, __bfloat162float(y01.y), c1) + fmaf(a2, zd.y, c2);
    r.z = fmaf(a1, __bfloat162float(y23.x), c1) + fmaf(a2, zd.z, c2);
    r.w = fmaf(a1, __bfloat162float(y23.y), c1) + fmaf(a2, zd.w, c2);
    ((float4*)out)[idx] = r;
}

// ---------------- launcher -------------------------------------------------
extern "C" void kernel_launch(void* const* d_in, const int* in_sizes, int n_in,
                              void* d_out, int out_size) {
    const float* x     = (const float*)d_in[0];
    const float* A     = (const float*)d_in[1];
    const float* PA    = (const float*)d_in[2];
    const float* Wa    = (const float*)d_in[3];
    const float* ba    = (const float*)d_in[4];
    const float* Wb    = (const float*)d_in[5];
    const float* bb    = (const float*)d_in[6];
    const float* Wd    = (const float*)d_in[7];
    const float* bd    = (const float*)d_in[8];
    const float* Wdown = (const float*)d_in[9];
    const float* bdown = (const float*)d_in[10];
    const float* gbn   = (const float*)d_in[11];
    const float* bbn   = (const float*)d_in[12];
    const float* gdn   = (const float*)d_in[13];
    const float* bdn   = (const float*)d_in[14];
    float* out = (float*)d_out;

    prep_kernel<<<48, 256>>>(Wa, ba, Wb, bb, Wd, bd, Wdown, A, PA);

    // a|b -> g_abh (bf16, staged stores) + down -> g_zd (fp32)+stats
    gemm_abdn_k<<<dim3(50, 3, 64), 256>>>(x, bdown);

    logits_mma_kernel<<<dim3(3, 64, 4), 256>>>();
    softmax_kernel<<<19, 256>>>();
    xs_mma_kernel<<<dim3(64, 64), 256>>>(x);      // xs -> g_xsb (coalesced bf16)

    gemm_y_k<<<dim3(50, 1, 64), 256>>>();         // y -> g_zy (staged bf16) + stats

    stats_reduce<<<256, 256>>>(gbn, bbn, gdn, bdn);
    final_kernel<<<51200, 256>>>(out);
}

// round 12
// speedup vs baseline: 4.3634x; 1.1049x over previous
#include <cuda_runtime.h>
#include <cuda_bf16.h>
#include <cstdint>

#define TV 6400           // T*V = 256*25
#define NBATCH 64

// ---------------- scratch (device globals; no allocation allowed) ----------
__device__ __nv_bfloat16 g_xsb[78643200];  // (64,192,6400) bf16: xs (S-mixed x)
__device__ __nv_bfloat16 g_zy[52428800];   // (64,128,6400) bf16: y pre-BN
__device__ float g_zd[52428800];           // (64,128,6400) fp32: down pre-BN
__device__ float g_part[3840000];   // (64,3,32,625) logits partials, [w*25+v]
__device__ float g_S[120000];       // (64,3,25,25) S^T: [w][v]
__device__ float g_Atot[1875];      // A + PA  ([v][w])
__device__ float g_by[128];         // sum_i bd[i]
__device__ float g_bab_pad[256];    // [ba|bb|0pad]
__device__ float g_alpha[256];      // BN fused scale
__device__ float g_bet[256];        // BN fused shift
__device__ float g_psum[819200];    // (2,64,50,128) per-block channel sums
__device__ float g_psq[819200];     // (2,64,50,128) per-block channel sumsq
// weights pre-packed in m16n8k16 A-fragment order (hi uint4 then lo uint4 per lane)
__device__ __align__(16) unsigned g_Wabf[16384];  // 16 mb x 4 ks x 32 x 8
__device__ __align__(16) unsigned g_Wyf[24576];   // 8 mb x 12 ks x 32 x 8
__device__ __align__(16) unsigned g_Wdnf[8192];   // 8 mb x 4 ks x 32 x 8

// ---------------- bf16 hi/lo split helpers ---------------------------------
__device__ __forceinline__ unsigned short bf_hi(float v) {
    return __bfloat16_as_ushort(__float2bfloat16(v));
}
__device__ __forceinline__ unsigned short bf_lo(float v) {
    __nv_bfloat16 h = __float2bfloat16(v);
    return __bfloat16_as_ushort(__float2bfloat16(v - __bfloat162float(h)));
}
__device__ __forceinline__ unsigned pack_hi(float v0, float v1) {
    return (unsigned)bf_hi(v0) | ((unsigned)bf_hi(v1) << 16);
}
__device__ __forceinline__ unsigned pack_lo(float v0, float v1) {
    return (unsigned)bf_lo(v0) | ((unsigned)bf_lo(v1) << 16);
}

// ---------------- prep: biases, A+PA, fragment-packed weights --------------
__device__ __forceinline__ void frag_decode(int f, int nK16,
                                            int& row, int& col, bool& hi) {
    int r = f & 7, slot = f >> 3;
    int lane = slot & 31, t2 = slot >> 5;
    int ks = t2 % nK16, mb = t2 / nK16;
    int rr = r & 3;
    row = mb * 16 + (lane >> 2) + ((rr & 1) << 3);
    col = ks * 16 + (lane & 3) * 2 + ((rr & 2) << 2);
    hi = r < 4;
}

__global__ __launch_bounds__(256) void prep_kernel(
    const float* __restrict__ Wa, const float* __restrict__ ba,
    const float* __restrict__ Wb, const float* __restrict__ bb,
    const float* __restrict__ Wd, const float* __restrict__ bd,
    const float* __restrict__ Wdown,
    const float* __restrict__ A,  const float* __restrict__ PA)
{
    int stride = gridDim.x * blockDim.x;
    int g = blockIdx.x * blockDim.x + threadIdx.x;
    for (int f = g; f < 256; f += stride)
        g_bab_pad[f] = (f < 96) ? ba[f] : (f < 192 ? bb[f - 96] : 0.f);
    for (int f = g; f < 128; f += stride)
        g_by[f] = bd[f] + bd[128 + f] + bd[256 + f];
    for (int f = g; f < 1875; f += stride)
        g_Atot[f] = A[f] + PA[f];

    for (int f = g; f < 16384; f += stride) {
        int row, col; bool hi;
        frag_decode(f, 4, row, col, hi);
        float v0 = 0.f, v1 = 0.f;
        if (row < 96)       { v0 = Wa[row * 64 + col]; v1 = Wa[row * 64 + col + 1]; }
        else if (row < 192) { v0 = Wb[(row - 96) * 64 + col]; v1 = Wb[(row - 96) * 64 + col + 1]; }
        g_Wabf[f] = hi ? pack_hi(v0, v1) : pack_lo(v0, v1);
    }
    for (int f = g; f < 24576; f += stride) {
        int row, col; bool hi;
        frag_decode(f, 12, row, col, hi);
        int i = col >> 6, c = col & 63;
        float v0 = Wd[(i * 128 + row) * 64 + c];
        float v1 = Wd[(i * 128 + row) * 64 + c + 1];
        g_Wyf[f] = hi ? pack_hi(v0, v1) : pack_lo(v0, v1);
    }
    for (int f = g; f < 8192; f += stride) {
        int row, col; bool hi;
        frag_decode(f, 4, row, col, hi);
        float v0 = Wdown[row * 64 + col], v1 = Wdown[row * 64 + col + 1];
        g_Wdnf[f] = hi ? pack_hi(v0, v1) : pack_lo(v0, v1);
    }
}

// ---------------- mma.sync wrapper -----------------------------------------
__device__ __forceinline__ void mma16816(float* c, const uint4& a,
                                         unsigned b0, unsigned b1) {
    asm volatile(
        "mma.sync.aligned.m16n8k16.row.col.f32.bf16.bf16.f32 "
        "{%0,%1,%2,%3}, {%4,%5,%6,%7}, {%8,%9}, {%0,%1,%2,%3};"
        : "+f"(c[0]), "+f"(c[1]), "+f"(c[2]), "+f"(c[3])
        : "r"(a.x), "r"(a.y), "r"(a.z), "r"(a.w), "r"(b0), "r"(b1));
}

// ========== fused a/b conv + logits partials; no a/b gmem round-trip =======
// grid (32 pt, 64 n); P-tile = 200 positions (8 whole t's). Block 256.
#define XP 66    // Xh pitch (odd word stride -> conflict-free)
#define AP 136   // At/Bt pitch

__global__ __launch_bounds__(256, 2) void ablogits_k(const float* __restrict__ x) {
    __shared__ __align__(16) unsigned short Xh[200][XP];
    __shared__ __align__(16) unsigned short At[32][AP];  // a^T: [v][r*8+tl]
    __shared__ __align__(16) unsigned short Bt[32][AP];  // b^T: [w][r*8+tl]
    int tid = threadIdx.x, wid = tid >> 5, lane = tid & 31;
    int pt = blockIdx.x, n = blockIdx.y;
    int lr = lane >> 2, lc2 = (lane & 3) * 2;
    int pBase = pt * 200;

    // stage X tile: 64 ch x 200 pos, bf16-hi, pos-major
    const float* xb = x + (long)n * (64L * TV) + pBase;
    for (int f = tid; f < 12800; f += 256) {
        int c = f / 200, p = f - c * 200;
        Xh[p][c] = bf_hi(xb[(long)c * TV + p]);
    }

    int ab = wid >> 2;        // 0: a rows, 1: b rows
    int q  = wid & 3;         // position quarter / w-tile
    int nt0 = q * 7, ntN = (q == 3) ? 4 : 7;
    float* outbase = g_part + ((long)n * 96 + pt) * 625;

    for (int i = 0; i < 3; i++) {
        float acc2[4] = {0.f, 0.f, 0.f, 0.f};
#pragma unroll
        for (int h = 0; h < 2; h++) {     // r-halves (16 rows each)
            __syncthreads();   // Xh staged / previous logits reads done
            // ---- a/b mma: one m16 row-tile x ntN n8 pos-tiles, K=64 ----
            float acc1[7][4] = {};
            int mb = ab ? (6 + 2 * i + h) : (2 * i + h);
#pragma unroll
            for (int ks = 0; ks < 4; ks++) {
                const uint4* fp = (const uint4*)g_Wabf + ((long)(mb * 4 + ks) * 32 + lane) * 2;
                uint4 Ah = fp[0];
                int bk = ks * 16 + lc2;
#pragma unroll
                for (int j = 0; j < 7; j++) {
                    if (j < ntN) {
                        int bp = (nt0 + j) * 8 + lr;
                        unsigned b0 = *(const unsigned*)&Xh[bp][bk];
                        unsigned b1 = *(const unsigned*)&Xh[bp][bk + 8];
                        mma16816(acc1[j], Ah, b0, b1);
                    }
                }
            }
            // ---- epilogue: +bias, transpose into At/Bt ----
            int growBase = (ab ? 96 : 0) + 32 * i + h * 16;
            float bs0 = g_bab_pad[growBase + lr];
            float bs1 = g_bab_pad[growBase + lr + 8];
            unsigned short (*Dt)[AP] = ab ? Bt : At;
#pragma unroll
            for (int j = 0; j < 7; j++) {
                if (j < ntN) {
                    int p0 = (nt0 + j) * 8 + lc2;
                    int v0 = p0 % 25, t0 = p0 / 25;
                    int p1 = p0 + 1;
                    int v1 = p1 % 25, t1 = p1 / 25;
                    Dt[v0][lr * 8 + t0]       = bf_hi(acc1[j][0] + bs0);
                    Dt[v1][lr * 8 + t1]       = bf_hi(acc1[j][1] + bs0);
                    Dt[v0][(lr + 8) * 8 + t0] = bf_hi(acc1[j][2] + bs1);
                    Dt[v1][(lr + 8) * 8 + t1] = bf_hi(acc1[j][3] + bs1);
                }
            }
            __syncthreads();
            // ---- logits mma: C[v][w] += sum_{k=128} At[v][k] Bt[w][k] ----
            int vr = ab * 16 + lr;     // warp's v rows
            int wr = q * 8 + lr;       // warp's w rows
#pragma unroll
            for (int ks = 0; ks < 8; ks++) {
                int kb = ks * 16 + lc2;
                uint4 Af;
                Af.x = *(const unsigned*)&At[vr][kb];
                Af.y = *(const unsigned*)&At[vr + 8][kb];
                Af.z = *(const unsigned*)&At[vr][kb + 8];
                Af.w = *(const unsigned*)&At[vr + 8][kb + 8];
                unsigned bb0 = *(const unsigned*)&Bt[wr][kb];
                unsigned bb1 = *(const unsigned*)&Bt[wr][kb + 8];
                mma16816(acc2, Af, bb0, bb1);
            }
        }
        // store partial logits, transposed [w*25+v]
        float* outp = outbase + (long)i * 32 * 625;
        int v = ab * 16 + lr, w = q * 8 + lc2;
        if (w < 25) {
            if (v < 25)     outp[w * 25 + v]     = acc2[0];
            if (v + 8 < 25) outp[w * 25 + v + 8] = acc2[2];
            if (w + 1 < 25) {
                if (v < 25)     outp[(w + 1) * 25 + v]     = acc2[1];
                if (v + 8 < 25) outp[(w + 1) * 25 + v + 8] = acc2[3];
            }
        }
    }
}

#define LDB 72   // smem row pitch for 128-wide GEMM staging

// =============== GEMM: down = Wdown @ x, 3-term, fp32 out, + stats =========
// grid (50, 1, 64)
__global__ __launch_bounds__(256, 2) void gemm_down_k(const float* __restrict__ x,
                                                      const float* __restrict__ bdown) {
    __shared__ __align__(16) unsigned short Bh[128][LDB];
    __shared__ __align__(16) unsigned short Bl[128][LDB];
    __shared__ float redS[8][8][4], redQ[8][8][4];
    int tid = threadIdx.x, wid = tid >> 5, lane = tid & 31;
    int n = blockIdx.z, pBase = blockIdx.x * 128;
    int warpM = (wid >> 1) * 32, warpP = (wid & 1) * 64;
    float acc[2][8][4] = {};

    const float* inp = x + (long)n * (64L * TV) + pBase;
    int sp = tid & 127, skh = (tid >> 7) * 32;
    const float* colp = inp + (long)skh * TV + sp;
#pragma unroll
    for (int j = 0; j < 32; j += 2) {
        float v0 = colp[(long)j * TV];
        float v1 = colp[(long)(j + 1) * TV];
        *(unsigned*)&Bh[sp][skh + j] = pack_hi(v0, v1);
        *(unsigned*)&Bl[sp][skh + j] = pack_lo(v0, v1);
    }
    __syncthreads();

#pragma unroll
    for (int ks = 0; ks < 4; ks++) {
        uint4 Ah[2], Al[2];
#pragma unroll
        for (int mi = 0; mi < 2; mi++) {
            int mb = (wid >> 1) * 2 + mi;
            const uint4* fp = (const uint4*)g_Wdnf + ((long)(mb * 4 + ks) * 32 + lane) * 2;
            Ah[mi] = fp[0];
            Al[mi] = fp[1];
        }
        int bk = ks * 16 + (lane & 3) * 2;
#pragma unroll
        for (int ni = 0; ni < 8; ni++) {
            int bp = warpP + ni * 8 + (lane >> 2);
            unsigned bh0 = *(const unsigned*)&Bh[bp][bk];
            unsigned bh1 = *(const unsigned*)&Bh[bp][bk + 8];
            unsigned bl0 = *(const unsigned*)&Bl[bp][bk];
            unsigned bl1 = *(const unsigned*)&Bl[bp][bk + 8];
#pragma unroll
            for (int mi = 0; mi < 2; mi++) {
                mma16816(acc[mi][ni], Ah[mi], bh0, bh1);
                mma16816(acc[mi][ni], Ah[mi], bl0, bl1);
                mma16816(acc[mi][ni], Al[mi], bh0, bh1);
            }
        }
    }

    float ssum[2][2] = {}, ssq[2][2] = {};
#pragma unroll
    for (int mi = 0; mi < 2; mi++) {
        int m = warpM + mi * 16 + (lane >> 2);
        float b0 = bdown[m], b1 = bdown[m + 8];
        float* op = g_zd + ((long)n * 128 + m) * TV + pBase + warpP + (lane & 3) * 2;
#pragma unroll
        for (int ni = 0; ni < 8; ni++) {
            float v0 = acc[mi][ni][0] + b0, v1 = acc[mi][ni][1] + b0;
            float v2 = acc[mi][ni][2] + b1, v3 = acc[mi][ni][3] + b1;
            *(float2*)(op + ni * 8) = make_float2(v0, v1);
            *(float2*)(op + ni * 8 + 8L * TV) = make_float2(v2, v3);
            ssum[mi][0] += v0 + v1; ssq[mi][0] += v0 * v0 + v1 * v1;
            ssum[mi][1] += v2 + v3; ssq[mi][1] += v2 * v2 + v3 * v3;
        }
    }
#pragma unroll
    for (int mi = 0; mi < 2; mi++)
#pragma unroll
        for (int hi = 0; hi < 2; hi++) {
            float s = ssum[mi][hi], q = ssq[mi][hi];
            s += __shfl_xor_sync(0xffffffffu, s, 1);
            s += __shfl_xor_sync(0xffffffffu, s, 2);
            q += __shfl_xor_sync(0xffffffffu, q, 1);
            q += __shfl_xor_sync(0xffffffffu, q, 2);
            if ((lane & 3) == 0) {
                redS[wid][lane >> 2][mi * 2 + hi] = s;
                redQ[wid][lane >> 2][mi * 2 + hi] = q;
            }
        }
    __syncthreads();
    if (tid < 128) {
        int r = tid, mt = r >> 5, rr = r & 31;
        int mi = rr >> 4, hi = (rr >> 3) & 1, q8 = rr & 7;
        int w0 = mt * 2;
        float S = redS[w0][q8][mi * 2 + hi] + redS[w0 + 1][q8][mi * 2 + hi];
        float Q = redQ[w0][q8][mi * 2 + hi] + redQ[w0 + 1][q8][mi * 2 + hi];
        long idx = (((long)64 + n) * 50 + blockIdx.x) * 128 + r;
        g_psum[idx] = S;
        g_psq[idx] = Q;
    }
}

// ---------------- softmax v2: block per (n,i), smem partial reduce ---------
__global__ __launch_bounds__(256) void softmax2_k() {
    __shared__ float P[625];
    int bx = blockIdx.x;
    int n = bx / 3, i = bx % 3;
    int tid = threadIdx.x;
    const float* base = g_part + ((long)(n * 3 + i)) * 32 * 625;
    for (int f = tid; f < 625; f += 256) {
        float s = 0.f;
#pragma unroll
        for (int pt = 0; pt < 32; pt++) s += base[pt * 625 + f];
        P[f] = s * (1.f / 8192.f);
    }
    __syncthreads();
    if (tid < 25) {
        int w = tid;
        float lg[25];
        float mx = -1e30f;
#pragma unroll
        for (int v = 0; v < 25; v++) { lg[v] = P[w * 25 + v]; mx = fmaxf(mx, lg[v]); }
        float sum = 0.f;
#pragma unroll
        for (int v = 0; v < 25; v++) { lg[v] = expf(lg[v] - mx); sum += lg[v]; }
        float inv = 1.f / sum;
        float* sp = g_S + (long)(n * 3 + i) * 625 + w * 25;
        const float* at = g_Atot + i * 625;
#pragma unroll
        for (int v = 0; v < 25; v++) sp[v] = lg[v] * inv + at[v * 25 + w];
    }
}

// ============ xs via mma: OUT[m,w] = sum_v IN[m,v] S[v,w], per (n,i) =======
__global__ __launch_bounds__(256) void xs_mma_kernel(const float* __restrict__ x) {
    __shared__ unsigned short As[256][40];
    __shared__ unsigned short Ss[3][32][40];   // [i][w][v]
    __shared__ __align__(16) unsigned short Os[6400];
    int tid = threadIdx.x, wid = tid >> 5, lane = tid & 31;
    int n = blockIdx.y, mt = blockIdx.x;
    int lr = lane >> 2, kb = (lane & 3) * 2;

    for (int f = tid; f < 5120; f += 256) ((unsigned*)As)[f] = 0;
    for (int f = tid; f < 1920; f += 256) ((unsigned*)Ss)[f] = 0;
    __syncthreads();

    const float* spt = g_S + (long)n * 1875;   // S^T: [i][w][v]
    for (int f = tid; f < 1875; f += 256) {
        int i = f / 625, r = f - i * 625, w = r / 25, v = r - w * 25;
        Ss[i][w][v] = bf_hi(spt[f]);
    }
    const float* xb = x + (long)n * 409600 + (long)mt * 6400;
    for (int f = tid; f < 6400; f += 256) {
        int m = f / 25, v = f - m * 25;
        As[m][v] = bf_hi(xb[f]);
    }
    __syncthreads();

    for (int i = 0; i < 3; i++) {
        float acc[2][4][4] = {};
#pragma unroll
        for (int ksx = 0; ksx < 2; ksx++) {
            uint4 Af[2];
#pragma unroll
            for (int mi = 0; mi < 2; mi++) {
                int mrow = wid * 32 + mi * 16 + lr;
                Af[mi].x = *(const unsigned*)&As[mrow][ksx * 16 + kb];
                Af[mi].y = *(const unsigned*)&As[mrow + 8][ksx * 16 + kb];
                Af[mi].z = *(const unsigned*)&As[mrow][ksx * 16 + kb + 8];
                Af[mi].w = *(const unsigned*)&As[mrow + 8][ksx * 16 + kb + 8];
            }
#pragma unroll
            for (int nt = 0; nt < 4; nt++) {
                unsigned b0 = *(const unsigned*)&Ss[i][nt * 8 + lr][ksx * 16 + kb];
                unsigned b1 = *(const unsigned*)&Ss[i][nt * 8 + lr][ksx * 16 + kb + 8];
                mma16816(acc[0][nt], Af[0], b0, b1);
                mma16816(acc[1][nt], Af[1], b0, b1);
            }
        }
#pragma unroll
        for (int mi = 0; mi < 2; mi++) {
            int mrow = wid * 32 + mi * 16 + lr;
#pragma unroll
            for (int nt = 0; nt < 4; nt++) {
                int w = nt * 8 + kb;
                if (w < 25) {
                    Os[mrow * 25 + w] = bf_hi(acc[mi][nt][0]);
                    Os[(mrow + 8) * 25 + w] = bf_hi(acc[mi][nt][2]);
                    if (w + 1 < 25) {
                        Os[mrow * 25 + w + 1] = bf_hi(acc[mi][nt][1]);
                        Os[(mrow + 8) * 25 + w + 1] = bf_hi(acc[mi][nt][3]);
                    }
                }
            }
        }
        __syncthreads();
        const uint4* os4 = (const uint4*)Os;
        uint4* ob4 = (uint4*)(g_xsb + (long)(n * 192 + i * 64 + mt) * 6400);
        for (int f = tid; f < 800; f += 256) ob4[f] = os4[f];
        __syncthreads();
    }
}

// =============== GEMM: y = Wd_cat @ xs, bf16 in/out, + stats ===============
__global__ __launch_bounds__(256, 2) void gemm_y_k() {
    __shared__ __align__(16) unsigned short Bh[128][LDB];
    __shared__ float redS[8][8][4], redQ[8][8][4];
    int tid = threadIdx.x, wid = tid >> 5, lane = tid & 31;
    int n = blockIdx.z, pBase = blockIdx.x * 128;
    int warpM = (wid >> 1) * 32, warpP = (wid & 1) * 64;
    float acc[2][8][4] = {};

    const __nv_bfloat16* inb = g_xsb + (long)n * (192L * TV) + pBase;
    int pq = tid & 63, skq = (tid >> 6) * 16;

    for (int kc = 0; kc < 3; kc++) {
        __syncthreads();
        const __nv_bfloat16* colb = inb + (long)(kc * 64 + skq) * TV + pq * 2;
#pragma unroll
        for (int j = 0; j < 16; j++) {
            __nv_bfloat162 v = *(const __nv_bfloat162*)(colb + (long)j * TV);
            Bh[pq * 2][skq + j]     = __bfloat16_as_ushort(v.x);
            Bh[pq * 2 + 1][skq + j] = __bfloat16_as_ushort(v.y);
        }
        __syncthreads();
#pragma unroll
        for (int ks = 0; ks < 4; ks++) {
            int kg = kc * 4 + ks;
            uint4 Ah[2];
#pragma unroll
            for (int mi = 0; mi < 2; mi++) {
                int mb = (wid >> 1) * 2 + mi;
                const uint4* fp = (const uint4*)g_Wyf + ((long)(mb * 12 + kg) * 32 + lane) * 2;
                Ah[mi] = fp[0];
            }
            int bk = ks * 16 + (lane & 3) * 2;
#pragma unroll
            for (int ni = 0; ni < 8; ni++) {
                int bp = warpP + ni * 8 + (lane >> 2);
                unsigned bh0 = *(const unsigned*)&Bh[bp][bk];
                unsigned bh1 = *(const unsigned*)&Bh[bp][bk + 8];
#pragma unroll
                for (int mi = 0; mi < 2; mi++)
                    mma16816(acc[mi][ni], Ah[mi], bh0, bh1);
            }
        }
    }

    float ssum[2][2] = {}, ssq[2][2] = {};
#pragma unroll
    for (int mi = 0; mi < 2; mi++) {
        int m = warpM + mi * 16 + (lane >> 2);
        float b0 = g_by[m], b1 = g_by[m + 8];
#pragma unroll
        for (int ni = 0; ni < 8; ni++) {
            float v0 = acc[mi][ni][0] + b0, v1 = acc[mi][ni][1] + b0;
            float v2 = acc[mi][ni][2] + b1, v3 = acc[mi][ni][3] + b1;
            ssum[mi][0] += v0 + v1; ssq[mi][0] += v0 * v0 + v1 * v1;
            ssum[mi][1] += v2 + v3; ssq[mi][1] += v2 * v2 + v3 * v3;
        }
    }
#pragma unroll
    for (int mi = 0; mi < 2; mi++)
#pragma unroll
        for (int hi = 0; hi < 2; hi++) {
            float s = ssum[mi][hi], q = ssq[mi][hi];
            s += __shfl_xor_sync(0xffffffffu, s, 1);
            s += __shfl_xor_sync(0xffffffffu, s, 2);
            q += __shfl_xor_sync(0xffffffffu, q, 1);
            q += __shfl_xor_sync(0xffffffffu, q, 2);
            if ((lane & 3) == 0) {
                redS[wid][lane >> 2][mi * 2 + hi] = s;
                redQ[wid][lane >> 2][mi * 2 + hi] = q;
            }
        }
    __syncthreads();
    if (tid < 128) {
        int r = tid, mt = r >> 5, rr = r & 31;
        int mi = rr >> 4, hi = (rr >> 3) & 1, q8 = rr & 7;
        int w0 = mt * 2;
        float S = redS[w0][q8][mi * 2 + hi] + redS[w0 + 1][q8][mi * 2 + hi];
        float Q = redQ[w0][q8][mi * 2 + hi] + redQ[w0 + 1][q8][mi * 2 + hi];
        long idx = ((long)n * 50 + blockIdx.x) * 128 + r;
        g_psum[idx] = S;
        g_psq[idx] = Q;
    }

    __syncthreads();
    unsigned short (*St)[136] = (unsigned short(*)[136])Bh;
#pragma unroll
    for (int h = 0; h < 2; h++) {
        if ((wid >> 2) == h) {
#pragma unroll
            for (int mi = 0; mi < 2; mi++) {
                int m = warpM + mi * 16 + (lane >> 2);
                float b0 = g_by[m], b1 = g_by[m + 8];
                int r0 = warpM - h * 64 + mi * 16 + (lane >> 2);
#pragma unroll
                for (int ni = 0; ni < 8; ni++) {
                    int col = warpP + ni * 8 + (lane & 3) * 2;
                    __nv_bfloat162 p0, p1;
                    p0.x = __float2bfloat16(acc[mi][ni][0] + b0);
                    p0.y = __float2bfloat16(acc[mi][ni][1] + b0);
                    p1.x = __float2bfloat16(acc[mi][ni][2] + b1);
                    p1.y = __float2bfloat16(acc[mi][ni][3] + b1);
                    *(__nv_bfloat162*)&St[r0][col] = p0;
                    *(__nv_bfloat162*)&St[r0 + 8][col] = p1;
                }
            }
        }
        __syncthreads();
        int m0 = h * 64;
        for (int f = tid; f < 1024; f += 256) {
            int r = f >> 4, c = f & 15;
            uint4 v = *(const uint4*)&St[r][c * 8];
            *(uint4*)(g_zy + ((long)n * 128 + m0 + r) * TV + pBase + c * 8) = v;
        }
        __syncthreads();
    }
}

// ---------------- stats reduce: per-channel mean/var from block partials ---
__global__ __launch_bounds__(256) void stats_reduce(
    const float* __restrict__ gbn, const float* __restrict__ bbn,
    const float* __restrict__ gdn, const float* __restrict__ bdn)
{
    int qch = blockIdx.x;
    int half = qch >> 7, r = qch & 127;
    int tid = threadIdx.x;
    float s = 0.f, q = 0.f;
    for (int f = tid; f < 3200; f += 256) {
        long idx = (((long)half * 64 + f / 50) * 50 + (f % 50)) * 128 + r;
        s += g_psum[idx];
        q += g_psq[idx];
    }
    __shared__ float rs[256], rq[256];
    rs[tid] = s; rq[tid] = q;
    __syncthreads();
    for (int st = 128; st > 0; st >>= 1) {
        if (tid < st) { rs[tid] += rs[tid + st]; rq[tid] += rq[tid + st]; }
        __syncthreads();
    }
    if (tid == 0) {
        const float inv_m = 1.f / 409600.f;
        float mean = rs[0] * inv_m;
        float var  = rq[0] * inv_m - mean * mean;
        float rinv = rsqrtf(var + 1e-5f);
        float gamma = half ? gdn[r] : gbn[r];
        float beta  = half ? bdn[r] : bbn[r];
        g_alpha[qch] = gamma * rinv;
        g_bet[qch]   = beta - mean * gamma * rinv;
    }
}

// ---------------- fused epilogue: out = BN_y(y) + BN_d(down) ---------------
__global__ __launch_bounds__(256) void final_kernel(float* __restrict__ out) {
    int idx = blockIdx.x * 256 + threadIdx.x;
    int p4 = idx % 1600;
    int o  = (idx / 1600) & 127;
    int n  = idx / 204800;
    long e = ((long)n * 128 + o) * TV + p4 * 4;
    uint2 yb = *(const uint2*)(g_zy + e);
    __nv_bfloat162 y01 = *(__nv_bfloat162*)&yb.x;
    __nv_bfloat162 y23 = *(__nv_bfloat162*)&yb.y;
    float4 zd = *(const float4*)(g_zd + e);
    float a1 = g_alpha[o],       c1 = g_bet[o];
    float a2 = g_alpha[o + 128], c2 = g_bet[o + 128];
    float4 r;
    r.x = fmaf(a1, __bfloat162float(y01.x), c1) + fmaf(a2, zd.x, c2);
    r.y = fmaf(a1, __bfloat162float(y01.y), c1) + fmaf(a2, zd.y, c2);
    r.z = fmaf(a1, __bfloat162float(y23.x), c1) + fmaf(a2, zd.z, c2);
    r.w = fmaf(a1, __bfloat162float(y23.y), c1) + fmaf(a2, zd.w, c2);
    ((float4*)out)[idx] = r;
}

// ---------------- launcher -------------------------------------------------
extern "C" void kernel_launch(void* const* d_in, const int* in_sizes, int n_in,
                              void* d_out, int out_size) {
    const float* x     = (const float*)d_in[0];
    const float* A     = (const float*)d_in[1];
    const float* PA    = (const float*)d_in[2];
    const float* Wa    = (const float*)d_in[3];
    const float* ba    = (const float*)d_in[4];
    const float* Wb    = (const float*)d_in[5];
    const float* bb    = (const float*)d_in[6];
    const float* Wd    = (const float*)d_in[7];
    const float* bd    = (const float*)d_in[8];
    const float* Wdown = (const float*)d_in[9];
    const float* bdown = (const float*)d_in[10];
    const float* gbn   = (const float*)d_in[11];
    const float* bbn   = (const float*)d_in[12];
    const float* gdn   = (const float*)d_in[13];
    const float* bdn   = (const float*)d_in[14];
    float* out = (float*)d_out;

    prep_kernel<<<48, 256>>>(Wa, ba, Wb, bb, Wd, bd, Wdown, A, PA);

    ablogits_k<<<dim3(32, 64), 256>>>(x);            // a/b + logits partials, no a/b gmem
    gemm_down_k<<<dim3(50, 1, 64), 256>>>(x, bdown); // down -> g_zd + stats partials
    softmax2_k<<<192, 256>>>();                      // S^T -> g_S
    xs_mma_kernel<<<dim3(64, 64), 256>>>(x);         // xs -> g_xsb
    gemm_y_k<<<dim3(50, 1, 64), 256>>>();            // y -> g_zy + stats partials

    stats_reduce<<<256, 256>>>(gbn, bbn, gdn, bdn);
    final_kernel<<<51200, 256>>>(out);
}

// round 13
// speedup vs baseline: 4.4554x; 1.0211x over previous
#include <cuda_runtime.h>
#include <cuda_bf16.h>
#include <cuda_fp16.h>
#include <cstdint>

#define TV 6400           // T*V = 256*25
#define NBATCH 64

// ---------------- scratch (device globals; no allocation allowed) ----------
__device__ __nv_bfloat16 g_xsb[78643200];  // (64,192,6400) bf16: xs (S-mixed x)
__device__ __nv_bfloat16 g_zy[52428800];   // (64,128,6400) bf16: y pre-BN
__device__ __half g_zdh[52428800];         // (64,128,6400) fp16: down pre-BN
__device__ float g_part[3840000];   // (64,3,32,625) logits partials, [w*25+v]
__device__ float g_S[120000];       // (64,3,25,25) S^T: [w][v]
__device__ float g_Atot[1875];      // A + PA  ([v][w])
__device__ float g_by[128];         // sum_i bd[i]
__device__ float g_bab_pad[256];    // [ba|bb|0pad]
__device__ float g_alpha[256];      // BN fused scale
__device__ float g_bet[256];        // BN fused shift
__device__ float g_psum[819200];    // (2,64,50,128) per-block channel sums
__device__ float g_psq[819200];     // (2,64,50,128) per-block channel sumsq
// weights pre-packed in m16n8k16 A-fragment order (hi uint4 then lo uint4 per lane)
__device__ __align__(16) unsigned g_Wabf[16384];  // 16 mb x 4 ks x 32 x 8
__device__ __align__(16) unsigned g_Wyf[24576];   // 8 mb x 12 ks x 32 x 8
__device__ __align__(16) unsigned g_Wdnf[8192];   // 8 mb x 4 ks x 32 x 8

// ---------------- bf16 hi/lo split helpers ---------------------------------
__device__ __forceinline__ unsigned short bf_hi(float v) {
    return __bfloat16_as_ushort(__float2bfloat16(v));
}
__device__ __forceinline__ unsigned short bf_lo(float v) {
    __nv_bfloat16 h = __float2bfloat16(v);
    return __bfloat16_as_ushort(__float2bfloat16(v - __bfloat162float(h)));
}
__device__ __forceinline__ unsigned pack_hi(float v0, float v1) {
    return (unsigned)bf_hi(v0) | ((unsigned)bf_hi(v1) << 16);
}
__device__ __forceinline__ unsigned pack_lo(float v0, float v1) {
    return (unsigned)bf_lo(v0) | ((unsigned)bf_lo(v1) << 16);
}

// ---------------- prep: biases, A+PA, fragment-packed weights --------------
__device__ __forceinline__ void frag_decode(int f, int nK16,
                                            int& row, int& col, bool& hi) {
    int r = f & 7, slot = f >> 3;
    int lane = slot & 31, t2 = slot >> 5;
    int ks = t2 % nK16, mb = t2 / nK16;
    int rr = r & 3;
    row = mb * 16 + (lane >> 2) + ((rr & 1) << 3);
    col = ks * 16 + (lane & 3) * 2 + ((rr & 2) << 2);
    hi = r < 4;
}

__global__ __launch_bounds__(256) void prep_kernel(
    const float* __restrict__ Wa, const float* __restrict__ ba,
    const float* __restrict__ Wb, const float* __restrict__ bb,
    const float* __restrict__ Wd, const float* __restrict__ bd,
    const float* __restrict__ Wdown,
    const float* __restrict__ A,  const float* __restrict__ PA)
{
    int stride = gridDim.x * blockDim.x;
    int g = blockIdx.x * blockDim.x + threadIdx.x;
    for (int f = g; f < 256; f += stride)
        g_bab_pad[f] = (f < 96) ? ba[f] : (f < 192 ? bb[f - 96] : 0.f);
    for (int f = g; f < 128; f += stride)
        g_by[f] = bd[f] + bd[128 + f] + bd[256 + f];
    for (int f = g; f < 1875; f += stride)
        g_Atot[f] = A[f] + PA[f];

    for (int f = g; f < 16384; f += stride) {
        int row, col; bool hi;
        frag_decode(f, 4, row, col, hi);
        float v0 = 0.f, v1 = 0.f;
        if (row < 96)       { v0 = Wa[row * 64 + col]; v1 = Wa[row * 64 + col + 1]; }
        else if (row < 192) { v0 = Wb[(row - 96) * 64 + col]; v1 = Wb[(row - 96) * 64 + col + 1]; }
        g_Wabf[f] = hi ? pack_hi(v0, v1) : pack_lo(v0, v1);
    }
    for (int f = g; f < 24576; f += stride) {
        int row, col; bool hi;
        frag_decode(f, 12, row, col, hi);
        int i = col >> 6, c = col & 63;
        float v0 = Wd[(i * 128 + row) * 64 + c];
        float v1 = Wd[(i * 128 + row) * 64 + c + 1];
        g_Wyf[f] = hi ? pack_hi(v0, v1) : pack_lo(v0, v1);
    }
    for (int f = g; f < 8192; f += stride) {
        int row, col; bool hi;
        frag_decode(f, 4, row, col, hi);
        float v0 = Wdown[row * 64 + col], v1 = Wdown[row * 64 + col + 1];
        g_Wdnf[f] = hi ? pack_hi(v0, v1) : pack_lo(v0, v1);
    }
}

// ---------------- mma.sync wrapper -----------------------------------------
__device__ __forceinline__ void mma16816(float* c, const uint4& a,
                                         unsigned b0, unsigned b1) {
    asm volatile(
        "mma.sync.aligned.m16n8k16.row.col.f32.bf16.bf16.f32 "
        "{%0,%1,%2,%3}, {%4,%5,%6,%7}, {%8,%9}, {%0,%1,%2,%3};"
        : "+f"(c[0]), "+f"(c[1]), "+f"(c[2]), "+f"(c[3])
        : "r"(a.x), "r"(a.y), "r"(a.z), "r"(a.w), "r"(b0), "r"(b1));
}

// ========== fused a/b conv + logits partials; no a/b gmem round-trip =======
// grid (32 pt, 64 n); P-tile = 200 positions (8 whole t's). Block 256.
#define XP 66    // Xh pitch (odd word stride -> conflict-free)
#define AP 136   // At/Bt pitch

__global__ __launch_bounds__(256, 2) void ablogits_k(const float* __restrict__ x) {
    __shared__ __align__(16) unsigned short Xh[200][XP];
    __shared__ __align__(16) unsigned short At[32][AP];  // a^T: [v][r*8+tl]
    __shared__ __align__(16) unsigned short Bt[32][AP];  // b^T: [w][r*8+tl]
    int tid = threadIdx.x, wid = tid >> 5, lane = tid & 31;
    int pt = blockIdx.x, n = blockIdx.y;
    int lr = lane >> 2, lc2 = (lane & 3) * 2;
    int pBase = pt * 200;

    // stage X tile: 64 ch x 200 pos, bf16-hi, pos-major
    const float* xb = x + (long)n * (64L * TV) + pBase;
    for (int f = tid; f < 12800; f += 256) {
        int c = f / 200, p = f - c * 200;
        Xh[p][c] = bf_hi(xb[(long)c * TV + p]);
    }

    int ab = wid >> 2;        // 0: a rows, 1: b rows
    int q  = wid & 3;         // position quarter / w-tile
    int nt0 = q * 7, ntN = (q == 3) ? 4 : 7;
    float* outbase = g_part + ((long)n * 96 + pt) * 625;

    for (int i = 0; i < 3; i++) {
        float acc2[4] = {0.f, 0.f, 0.f, 0.f};
#pragma unroll
        for (int h = 0; h < 2; h++) {     // r-halves (16 rows each)
            __syncthreads();   // Xh staged / previous logits reads done
            // ---- a/b mma: one m16 row-tile x ntN n8 pos-tiles, K=64 ----
            float acc1[7][4] = {};
            int mb = ab ? (6 + 2 * i + h) : (2 * i + h);
#pragma unroll
            for (int ks = 0; ks < 4; ks++) {
                const uint4* fp = (const uint4*)g_Wabf + ((long)(mb * 4 + ks) * 32 + lane) * 2;
                uint4 Ah = fp[0];
                int bk = ks * 16 + lc2;
#pragma unroll
                for (int j = 0; j < 7; j++) {
                    if (j < ntN) {
                        int bp = (nt0 + j) * 8 + lr;
                        unsigned b0 = *(const unsigned*)&Xh[bp][bk];
                        unsigned b1 = *(const unsigned*)&Xh[bp][bk + 8];
                        mma16816(acc1[j], Ah, b0, b1);
                    }
                }
            }
            // ---- epilogue: +bias, transpose into At/Bt ----
            int growBase = (ab ? 96 : 0) + 32 * i + h * 16;
            float bs0 = g_bab_pad[growBase + lr];
            float bs1 = g_bab_pad[growBase + lr + 8];
            unsigned short (*Dt)[AP] = ab ? Bt : At;
#pragma unroll
            for (int j = 0; j < 7; j++) {
                if (j < ntN) {
                    int p0 = (nt0 + j) * 8 + lc2;
                    int v0 = p0 % 25, t0 = p0 / 25;
                    int p1 = p0 + 1;
                    int v1 = p1 % 25, t1 = p1 / 25;
                    Dt[v0][lr * 8 + t0]       = bf_hi(acc1[j][0] + bs0);
                    Dt[v1][lr * 8 + t1]       = bf_hi(acc1[j][1] + bs0);
                    Dt[v0][(lr + 8) * 8 + t0] = bf_hi(acc1[j][2] + bs1);
                    Dt[v1][(lr + 8) * 8 + t1] = bf_hi(acc1[j][3] + bs1);
                }
            }
            __syncthreads();
            // ---- logits mma: C[v][w] += sum_{k=128} At[v][k] Bt[w][k] ----
            int vr = ab * 16 + lr;     // warp's v rows
            int wr = q * 8 + lr;       // warp's w rows
#pragma unroll
            for (int ks = 0; ks < 8; ks++) {
                int kb = ks * 16 + lc2;
                uint4 Af;
                Af.x = *(const unsigned*)&At[vr][kb];
                Af.y = *(const unsigned*)&At[vr + 8][kb];
                Af.z = *(const unsigned*)&At[vr][kb + 8];
                Af.w = *(const unsigned*)&At[vr + 8][kb + 8];
                unsigned bb0 = *(const unsigned*)&Bt[wr][kb];
                unsigned bb1 = *(const unsigned*)&Bt[wr][kb + 8];
                mma16816(acc2, Af, bb0, bb1);
            }
        }
        // store partial logits, transposed [w*25+v]
        float* outp = outbase + (long)i * 32 * 625;
        int v = ab * 16 + lr, w = q * 8 + lc2;
        if (w < 25) {
            if (v < 25)     outp[w * 25 + v]     = acc2[0];
            if (v + 8 < 25) outp[w * 25 + v + 8] = acc2[2];
            if (w + 1 < 25) {
                if (v < 25)     outp[(w + 1) * 25 + v]     = acc2[1];
                if (v + 8 < 25) outp[(w + 1) * 25 + v + 8] = acc2[3];
            }
        }
    }
}

#define LDB 72   // smem row pitch for 128-wide GEMM staging

// =============== GEMM: down = Wdown @ x, 3-term, fp16 out, + stats =========
// grid (50, 1, 64)
__global__ __launch_bounds__(256, 2) void gemm_down_k(const float* __restrict__ x,
                                                      const float* __restrict__ bdown) {
    __shared__ __align__(16) unsigned short Bh[128][LDB];
    __shared__ __align__(16) unsigned short Bl[128][LDB];
    __shared__ float redS[8][8][4], redQ[8][8][4];
    int tid = threadIdx.x, wid = tid >> 5, lane = tid & 31;
    int n = blockIdx.z, pBase = blockIdx.x * 128;
    int warpM = (wid >> 1) * 32, warpP = (wid & 1) * 64;
    float acc[2][8][4] = {};

    const float* inp = x + (long)n * (64L * TV) + pBase;
    int sp = tid & 127, skh = (tid >> 7) * 32;
    const float* colp = inp + (long)skh * TV + sp;
#pragma unroll
    for (int j = 0; j < 32; j += 2) {
        float v0 = colp[(long)j * TV];
        float v1 = colp[(long)(j + 1) * TV];
        *(unsigned*)&Bh[sp][skh + j] = pack_hi(v0, v1);
        *(unsigned*)&Bl[sp][skh + j] = pack_lo(v0, v1);
    }
    __syncthreads();

#pragma unroll
    for (int ks = 0; ks < 4; ks++) {
        uint4 Ah[2], Al[2];
#pragma unroll
        for (int mi = 0; mi < 2; mi++) {
            int mb = (wid >> 1) * 2 + mi;
            const uint4* fp = (const uint4*)g_Wdnf + ((long)(mb * 4 + ks) * 32 + lane) * 2;
            Ah[mi] = fp[0];
            Al[mi] = fp[1];
        }
        int bk = ks * 16 + (lane & 3) * 2;
#pragma unroll
        for (int ni = 0; ni < 8; ni++) {
            int bp = warpP + ni * 8 + (lane >> 2);
            unsigned bh0 = *(const unsigned*)&Bh[bp][bk];
            unsigned bh1 = *(const unsigned*)&Bh[bp][bk + 8];
            unsigned bl0 = *(const unsigned*)&Bl[bp][bk];
            unsigned bl1 = *(const unsigned*)&Bl[bp][bk + 8];
#pragma unroll
            for (int mi = 0; mi < 2; mi++) {
                mma16816(acc[mi][ni], Ah[mi], bh0, bh1);
                mma16816(acc[mi][ni], Ah[mi], bl0, bl1);
                mma16816(acc[mi][ni], Al[mi], bh0, bh1);
            }
        }
    }

    float ssum[2][2] = {}, ssq[2][2] = {};
#pragma unroll
    for (int mi = 0; mi < 2; mi++) {
        int m = warpM + mi * 16 + (lane >> 2);
        float b0 = bdown[m], b1 = bdown[m + 8];
        __half* op = g_zdh + ((long)n * 128 + m) * TV + pBase + warpP + (lane & 3) * 2;
#pragma unroll
        for (int ni = 0; ni < 8; ni++) {
            float v0 = acc[mi][ni][0] + b0, v1 = acc[mi][ni][1] + b0;
            float v2 = acc[mi][ni][2] + b1, v3 = acc[mi][ni][3] + b1;
            __half2 h01 = make_half2(__float2half_rn(v0), __float2half_rn(v1));
            __half2 h23 = make_half2(__float2half_rn(v2), __float2half_rn(v3));
            *(__half2*)(op + ni * 8) = h01;
            *(__half2*)(op + ni * 8 + 8L * TV) = h23;
            ssum[mi][0] += v0 + v1; ssq[mi][0] += v0 * v0 + v1 * v1;
            ssum[mi][1] += v2 + v3; ssq[mi][1] += v2 * v2 + v3 * v3;
        }
    }
#pragma unroll
    for (int mi = 0; mi < 2; mi++)
#pragma unroll
        for (int hi = 0; hi < 2; hi++) {
            float s = ssum[mi][hi], q = ssq[mi][hi];
            s += __shfl_xor_sync(0xffffffffu, s, 1);
            s += __shfl_xor_sync(0xffffffffu, s, 2);
            q += __shfl_xor_sync(0xffffffffu, q, 1);
            q += __shfl_xor_sync(0xffffffffu, q, 2);
            if ((lane & 3) == 0) {
                redS[wid][lane >> 2][mi * 2 + hi] = s;
                redQ[wid][lane >> 2][mi * 2 + hi] = q;
            }
        }
    __syncthreads();
    if (tid < 128) {
        int r = tid, mt = r >> 5, rr = r & 31;
        int mi = rr >> 4, hi = (rr >> 3) & 1, q8 = rr & 7;
        int w0 = mt * 2;
        float S = redS[w0][q8][mi * 2 + hi] + redS[w0 + 1][q8][mi * 2 + hi];
        float Q = redQ[w0][q8][mi * 2 + hi] + redQ[w0 + 1][q8][mi * 2 + hi];
        long idx = (((long)64 + n) * 50 + blockIdx.x) * 128 + r;
        g_psum[idx] = S;
        g_psq[idx] = Q;
    }
}

// ---------------- softmax v3: block per n, 75 parallel softmaxes -----------
__global__ __launch_bounds__(256) void softmax3_k() {
    __shared__ float P[3][625];
    int n = blockIdx.x;
    int tid = threadIdx.x;
    const float* base = g_part + (long)n * 3 * 32 * 625;
    for (int f = tid; f < 1875; f += 256) {
        int i = f / 625, r = f - i * 625;
        const float* pp = base + (long)i * 32 * 625 + r;
        float s = 0.f;
#pragma unroll
        for (int pt = 0; pt < 32; pt++) s += pp[pt * 625];
        P[i][r] = s * (1.f / 8192.f);
    }
    __syncthreads();
    if (tid < 75) {
        int i = tid / 25, w = tid - i * 25;
        float lg[25];
        float mx = -1e30f;
#pragma unroll
        for (int v = 0; v < 25; v++) { lg[v] = P[i][w * 25 + v]; mx = fmaxf(mx, lg[v]); }
        float sum = 0.f;
#pragma unroll
        for (int v = 0; v < 25; v++) { lg[v] = expf(lg[v] - mx); sum += lg[v]; }
        float inv = 1.f / sum;
        float* sp = g_S + (long)(n * 3 + i) * 625 + w * 25;
        const float* at = g_Atot + i * 625;
#pragma unroll
        for (int v = 0; v < 25; v++) sp[v] = lg[v] * inv + at[v * 25 + w];
    }
}

// ============ xs via mma: OUT[m,w] = sum_v IN[m,v] S[v,w], per (n,i) =======
__global__ __launch_bounds__(256) void xs_mma_kernel(const float* __restrict__ x) {
    __shared__ unsigned short As[256][40];
    __shared__ unsigned short Ss[3][32][40];   // [i][w][v]
    __shared__ __align__(16) unsigned short Os[6400];
    int tid = threadIdx.x, wid = tid >> 5, lane = tid & 31;
    int n = blockIdx.y, mt = blockIdx.x;
    int lr = lane >> 2, kb = (lane & 3) * 2;

    for (int f = tid; f < 5120; f += 256) ((unsigned*)As)[f] = 0;
    for (int f = tid; f < 1920; f += 256) ((unsigned*)Ss)[f] = 0;
    __syncthreads();

    const float* spt = g_S + (long)n * 1875;   // S^T: [i][w][v]
    for (int f = tid; f < 1875; f += 256) {
        int i = f / 625, r = f - i * 625, w = r / 25, v = r - w * 25;
        Ss[i][w][v] = bf_hi(spt[f]);
    }
    const float* xb = x + (long)n * 409600 + (long)mt * 6400;
    for (int f = tid; f < 6400; f += 256) {
        int m = f / 25, v = f - m * 25;
        As[m][v] = bf_hi(xb[f]);
    }
    __syncthreads();

    for (int i = 0; i < 3; i++) {
        float acc[2][4][4] = {};
#pragma unroll
        for (int ksx = 0; ksx < 2; ksx++) {
            uint4 Af[2];
#pragma unroll
            for (int mi = 0; mi < 2; mi++) {
                int mrow = wid * 32 + mi * 16 + lr;
                Af[mi].x = *(const unsigned*)&As[mrow][ksx * 16 + kb];
                Af[mi].y = *(const unsigned*)&As[mrow + 8][ksx * 16 + kb];
                Af[mi].z = *(const unsigned*)&As[mrow][ksx * 16 + kb + 8];
                Af[mi].w = *(const unsigned*)&As[mrow + 8][ksx * 16 + kb + 8];
            }
#pragma unroll
            for (int nt = 0; nt < 4; nt++) {
                unsigned b0 = *(const unsigned*)&Ss[i][nt * 8 + lr][ksx * 16 + kb];
                unsigned b1 = *(const unsigned*)&Ss[i][nt * 8 + lr][ksx * 16 + kb + 8];
                mma16816(acc[0][nt], Af[0], b0, b1);
                mma16816(acc[1][nt], Af[1], b0, b1);
            }
        }
#pragma unroll
        for (int mi = 0; mi < 2; mi++) {
            int mrow = wid * 32 + mi * 16 + lr;
#pragma unroll
            for (int nt = 0; nt < 4; nt++) {
                int w = nt * 8 + kb;
                if (w < 25) {
                    Os[mrow * 25 + w] = bf_hi(acc[mi][nt][0]);
                    Os[(mrow + 8) * 25 + w] = bf_hi(acc[mi][nt][2]);
                    if (w + 1 < 25) {
                        Os[mrow * 25 + w + 1] = bf_hi(acc[mi][nt][1]);
                        Os[(mrow + 8) * 25 + w + 1] = bf_hi(acc[mi][nt][3]);
                    }
                }
            }
        }
        __syncthreads();
        const uint4* os4 = (const uint4*)Os;
        uint4* ob4 = (uint4*)(g_xsb + (long)(n * 192 + i * 64 + mt) * 6400);
        for (int f = tid; f < 800; f += 256) ob4[f] = os4[f];
        __syncthreads();
    }
}

// =============== GEMM: y = Wd_cat @ xs, bf16 in/out, + stats ===============
__global__ __launch_bounds__(256, 2) void gemm_y_k() {
    __shared__ __align__(16) unsigned short Bh[128][LDB];
    __shared__ float redS[8][8][4], redQ[8][8][4];
    int tid = threadIdx.x, wid = tid >> 5, lane = tid & 31;
    int n = blockIdx.z, pBase = blockIdx.x * 128;
    int warpM = (wid >> 1) * 32, warpP = (wid & 1) * 64;
    float acc[2][8][4] = {};

    const __nv_bfloat16* inb = g_xsb + (long)n * (192L * TV) + pBase;
    int pq = tid & 63, skq = (tid >> 6) * 16;

    for (int kc = 0; kc < 3; kc++) {
        __syncthreads();
        const __nv_bfloat16* colb = inb + (long)(kc * 64 + skq) * TV + pq * 2;
#pragma unroll
        for (int j = 0; j < 16; j++) {
            __nv_bfloat162 v = *(const __nv_bfloat162*)(colb + (long)j * TV);
            Bh[pq * 2][skq + j]     = __bfloat16_as_ushort(v.x);
            Bh[pq * 2 + 1][skq + j] = __bfloat16_as_ushort(v.y);
        }
        __syncthreads();
#pragma unroll
        for (int ks = 0; ks < 4; ks++) {
            int kg = kc * 4 + ks;
            uint4 Ah[2];
#pragma unroll
            for (int mi = 0; mi < 2; mi++) {
                int mb = (wid >> 1) * 2 + mi;
                const uint4* fp = (const uint4*)g_Wyf + ((long)(mb * 12 + kg) * 32 + lane) * 2;
                Ah[mi] = fp[0];
            }
            int bk = ks * 16 + (lane & 3) * 2;
#pragma unroll
            for (int ni = 0; ni < 8; ni++) {
                int bp = warpP + ni * 8 + (lane >> 2);
                unsigned bh0 = *(const unsigned*)&Bh[bp][bk];
                unsigned bh1 = *(const unsigned*)&Bh[bp][bk + 8];
#pragma unroll
                for (int mi = 0; mi < 2; mi++)
                    mma16816(acc[mi][ni], Ah[mi], bh0, bh1);
            }
        }
    }

    float ssum[2][2] = {}, ssq[2][2] = {};
#pragma unroll
    for (int mi = 0; mi < 2; mi++) {
        int m = warpM + mi * 16 + (lane >> 2);
        float b0 = g_by[m], b1 = g_by[m + 8];
#pragma unroll
        for (int ni = 0; ni < 8; ni++) {
            float v0 = acc[mi][ni][0] + b0, v1 = acc[mi][ni][1] + b0;
            float v2 = acc[mi][ni][2] + b1, v3 = acc[mi][ni][3] + b1;
            ssum[mi][0] += v0 + v1; ssq[mi][0] += v0 * v0 + v1 * v1;
            ssum[mi][1] += v2 + v3; ssq[mi][1] += v2 * v2 + v3 * v3;
        }
    }
#pragma unroll
    for (int mi = 0; mi < 2; mi++)
#pragma unroll
        for (int hi = 0; hi < 2; hi++) {
            float s = ssum[mi][hi], q = ssq[mi][hi];
            s += __shfl_xor_sync(0xffffffffu, s, 1);
            s += __shfl_xor_sync(0xffffffffu, s, 2);
            q += __shfl_xor_sync(0xffffffffu, q, 1);
            q += __shfl_xor_sync(0xffffffffu, q, 2);
            if ((lane & 3) == 0) {
                redS[wid][lane >> 2][mi * 2 + hi] = s;
                redQ[wid][lane >> 2][mi * 2 + hi] = q;
            }
        }
    __syncthreads();
    if (tid < 128) {
        int r = tid, mt = r >> 5, rr = r & 31;
        int mi = rr >> 4, hi = (rr >> 3) & 1, q8 = rr & 7;
        int w0 = mt * 2;
        float S = redS[w0][q8][mi * 2 + hi] + redS[w0 + 1][q8][mi * 2 + hi];
        float Q = redQ[w0][q8][mi * 2 + hi] + redQ[w0 + 1][q8][mi * 2 + hi];
        long idx = ((long)n * 50 + blockIdx.x) * 128 + r;
        g_psum[idx] = S;
        g_psq[idx] = Q;
    }

    __syncthreads();
    unsigned short (*St)[136] = (unsigned short(*)[136])Bh;
#pragma unroll
    for (int h = 0; h < 2; h++) {
        if ((wid >> 2) == h) {
#pragma unroll
            for (int mi = 0; mi < 2; mi++) {
                int m = warpM + mi * 16 + (lane >> 2);
                float b0 = g_by[m], b1 = g_by[m + 8];
                int r0 = warpM - h * 64 + mi * 16 + (lane >> 2);
#pragma unroll
                for (int ni = 0; ni < 8; ni++) {
                    int col = warpP + ni * 8 + (lane & 3) * 2;
                    __nv_bfloat162 p0, p1;
                    p0.x = __float2bfloat16(acc[mi][ni][0] + b0);
                    p0.y = __float2bfloat16(acc[mi][ni][1] + b0);
                    p1.x = __float2bfloat16(acc[mi][ni][2] + b1);
                    p1.y = __float2bfloat16(acc[mi][ni][3] + b1);
                    *(__nv_bfloat162*)&St[r0][col] = p0;
                    *(__nv_bfloat162*)&St[r0 + 8][col] = p1;
                }
            }
        }
        __syncthreads();
        int m0 = h * 64;
        for (int f = tid; f < 1024; f += 256) {
            int r = f >> 4, c = f & 15;
            uint4 v = *(const uint4*)&St[r][c * 8];
            *(uint4*)(g_zy + ((long)n * 128 + m0 + r) * TV + pBase + c * 8) = v;
        }
        __syncthreads();
    }
}

// ---------------- stats reduce: per-channel mean/var from block partials ---
__global__ __launch_bounds__(256) void stats_reduce(
    const float* __restrict__ gbn, const float* __restrict__ bbn,
    const float* __restrict__ gdn, const float* __restrict__ bdn)
{
    int qch = blockIdx.x;
    int half = qch >> 7, r = qch & 127;
    int tid = threadIdx.x;
    float s = 0.f, q = 0.f;
    for (int f = tid; f < 3200; f += 256) {
        long idx = (((long)half * 64 + f / 50) * 50 + (f % 50)) * 128 + r;
        s += g_psum[idx];
        q += g_psq[idx];
    }
    __shared__ float rs[256], rq[256];
    rs[tid] = s; rq[tid] = q;
    __syncthreads();
    for (int st = 128; st > 0; st >>= 1) {
        if (tid < st) { rs[tid] += rs[tid + st]; rq[tid] += rq[tid + st]; }
        __syncthreads();
    }
    if (tid == 0) {
        const float inv_m = 1.f / 409600.f;
        float mean = rs[0] * inv_m;
        float var  = rq[0] * inv_m - mean * mean;
        float rinv = rsqrtf(var + 1e-5f);
        float gamma = half ? gdn[r] : gbn[r];
        float beta  = half ? bdn[r] : bbn[r];
        g_alpha[qch] = gamma * rinv;
        g_bet[qch]   = beta - mean * gamma * rinv;
    }
}

// ---------------- fused epilogue: out = BN_y(y) + BN_d(down) ---------------
__global__ __launch_bounds__(256) void final_kernel(float* __restrict__ out) {
    int idx = blockIdx.x * 256 + threadIdx.x;
    int p4 = idx % 1600;
    int o  = (idx / 1600) & 127;
    int n  = idx / 204800;
    long e = ((long)n * 128 + o) * TV + p4 * 4;
    uint2 yb = *(const uint2*)(g_zy + e);
    __nv_bfloat162 y01 = *(__nv_bfloat162*)&yb.x;
    __nv_bfloat162 y23 = *(__nv_bfloat162*)&yb.y;
    uint2 db = *(const uint2*)(g_zdh + e);
    __half2 d01 = *(__half2*)&db.x;
    __half2 d23 = *(__half2*)&db.y;
    float a1 = g_alpha[o],       c1 = g_bet[o];
    float a2 = g_alpha[o + 128], c2 = g_bet[o + 128];
    float4 r;
    r.x = fmaf(a1, __bfloat162float(y01.x), c1) + fmaf(a2, __half2float(d01.x), c2);
    r.y = fmaf(a1, __bfloat162float(y01.y), c1) + fmaf(a2, __half2float(d01.y), c2);
    r.z = fmaf(a1, __bfloat162float(y23.x), c1) + fmaf(a2, __half2float(d23.x), c2);
    r.w = fmaf(a1, __bfloat162float(y23.y), c1) + fmaf(a2, __half2float(d23.y), c2);
    ((float4*)out)[idx] = r;
}

// ---------------- launcher -------------------------------------------------
extern "C" void kernel_launch(void* const* d_in, const int* in_sizes, int n_in,
                              void* d_out, int out_size) {
    const float* x     = (const float*)d_in[0];
    const float* A     = (const float*)d_in[1];
    const float* PA    = (const float*)d_in[2];
    const float* Wa    = (const float*)d_in[3];
    const float* ba    = (const float*)d_in[4];
    const float* Wb    = (const float*)d_in[5];
    const float* bb    = (const float*)d_in[6];
    const float* Wd    = (const float*)d_in[7];
    const float* bd    = (const float*)d_in[8];
    const float* Wdown = (const float*)d_in[9];
    const float* bdown = (const float*)d_in[10];
    const float* gbn   = (const float*)d_in[11];
    const float* bbn   = (const float*)d_in[12];
    const float* gdn   = (const float*)d_in[13];
    const float* bdn   = (const float*)d_in[14];
    float* out = (float*)d_out;

    // static side stream + events (created on the pre-capture correctness call)
    static cudaStream_t s_down = nullptr;
    static cudaEvent_t ev_fork = nullptr, ev_join = nullptr;
    if (!s_down) {
        cudaStreamCreateWithFlags(&s_down, cudaStreamNonBlocking);
        cudaEventCreateWithFlags(&ev_fork, cudaEventDisableTiming);
        cudaEventCreateWithFlags(&ev_join, cudaEventDisableTiming);
    }

    prep_kernel<<<48, 256>>>(Wa, ba, Wb, bb, Wd, bd, Wdown, A, PA);

    // fork: down branch runs concurrently with the attention chain
    cudaEventRecord(ev_fork, 0);
    cudaStreamWaitEvent(s_down, ev_fork, 0);
    gemm_down_k<<<dim3(50, 1, 64), 256, 0, s_down>>>(x, bdown);
    cudaEventRecord(ev_join, s_down);

    ablogits_k<<<dim3(32, 64), 256>>>(x);            // a/b + logits partials
    softmax3_k<<<64, 256>>>();                       // S^T -> g_S
    xs_mma_kernel<<<dim3(64, 64), 256>>>(x);         // xs -> g_xsb
    gemm_y_k<<<dim3(50, 1, 64), 256>>>();            // y -> g_zy + stats partials

    // join before stats (needs down's partials) and final (needs g_zdh)
    cudaStreamWaitEvent(0, ev_join, 0);
    stats_reduce<<<256, 256>>>(gbn, bbn, gdn, bdn);
    final_kernel<<<51200, 256>>>(out);
}